// round 1
// baseline (speedup 1.0000x reference)
#include <cuda_runtime.h>
#include <math.h>

#define Bsz  8
#define Cdim 256
#define Ntok 4096
#define ROWS (Bsz * Ntok)          // 32768 token rows
#define C4   (4 * Cdim)            // 1024

// ---------------- scratch (static device arrays; no allocation) ----------------
__device__ float g_x1[(size_t)ROWS * Cdim];        // x after qkv (loop-invariant)
__device__ float g_v[(size_t)ROWS * Cdim];         // v (updated per iter)
__device__ float g_sm[(size_t)ROWS * Cdim];        // softmax(x) (loop-invariant)
__device__ float g_u[(size_t)ROWS * Cdim];         // xt0 scratch, then pre-LN2 values
__device__ float g_cat2[(size_t)ROWS * C4];        // [out | v | mlp], ld=1024
__device__ float g_ctx[(size_t)Bsz * Cdim * Cdim]; // per-batch context
__device__ float g_mu[ROWS];
__device__ float g_rinv[ROWS];
__device__ float g_Wg[(size_t)Cdim * C4];          // g1[k] * W_res[c,k]
__device__ float g_S1[Cdim];
__device__ float g_S2[Cdim];

// ---------------- tiled transpose: in (R x Cc) -> out (Cc x R), batched in z ----
__global__ void transpose_k(const float* __restrict__ in, float* __restrict__ out,
                            int R, int Cc) {
    __shared__ float tile[32][33];
    size_t base = (size_t)blockIdx.z * R * Cc;
    in += base; out += base;
    int c0 = blockIdx.x * 32, r0 = blockIdx.y * 32;
    int tx = threadIdx.x, ty = threadIdx.y;  // 32x8
#pragma unroll
    for (int j = 0; j < 32; j += 8)
        tile[ty + j][tx] = in[(size_t)(r0 + ty + j) * Cc + c0 + tx];
    __syncthreads();
#pragma unroll
    for (int j = 0; j < 32; j += 8)
        out[(size_t)(c0 + ty + j) * R + r0 + tx] = tile[tx][ty + j];
}

// ---------------- softmax over rows of 256 (one warp per row) ------------------
__global__ void softmax_k(const float* __restrict__ x, float* __restrict__ y) {
    int row = blockIdx.x * 8 + (threadIdx.x >> 5);
    int lane = threadIdx.x & 31;
    const float* xr = x + (size_t)row * Cdim;
    float v[8];
    float mx = -1e30f;
#pragma unroll
    for (int i = 0; i < 8; i++) { v[i] = xr[lane + 32 * i]; mx = fmaxf(mx, v[i]); }
#pragma unroll
    for (int o = 16; o; o >>= 1) mx = fmaxf(mx, __shfl_xor_sync(0xffffffffu, mx, o));
    float s = 0.f;
#pragma unroll
    for (int i = 0; i < 8; i++) { v[i] = __expf(v[i] - mx); s += v[i]; }
#pragma unroll
    for (int o = 16; o; o >>= 1) s += __shfl_xor_sync(0xffffffffu, s, o);
    float inv = 1.f / s;
    float* yr = y + (size_t)row * Cdim;
#pragma unroll
    for (int i = 0; i < 8; i++) yr[lane + 32 * i] = v[i] * inv;
}

// ---------------- simple float4 copy -------------------------------------------
__global__ void copy_k(float* __restrict__ dst, const float* __restrict__ src, size_t n4) {
    size_t i = (size_t)blockIdx.x * blockDim.x + threadIdx.x;
    if (i < n4) ((float4*)dst)[i] = ((const float4*)src)[i];
}

// ---------------- copy v into cat2 columns [256,512) ----------------------------
__global__ void vcopy_k() {
    int i = blockIdx.x * 256 + threadIdx.x;     // over ROWS*64 float4s
    int m = i >> 6, c = i & 63;
    ((float4*)g_cat2)[(size_t)m * 256 + 64 + c] = ((const float4*)g_v)[(size_t)m * 64 + c];
}

// ---------------- precompute Wg = g1*W_res, S1, S2 (one warp per output c) ------
__global__ void prep_k(const float* __restrict__ Wres, const float* __restrict__ g1,
                       const float* __restrict__ beta1) {
    int c = blockIdx.x * 8 + (threadIdx.x >> 5);
    int lane = threadIdx.x & 31;
    const float* wr = Wres + (size_t)c * C4;
    float s1 = 0.f, s2 = 0.f;
    for (int k = lane; k < C4; k += 32) {
        float w = wr[k], g = g1[k];
        g_Wg[(size_t)c * C4 + k] = g * w;
        s1 += g * w;
        s2 += beta1[k] * w;
    }
#pragma unroll
    for (int o = 16; o; o >>= 1) {
        s1 += __shfl_xor_sync(0xffffffffu, s1, o);
        s2 += __shfl_xor_sync(0xffffffffu, s2, o);
    }
    if (lane == 0) { g_S1[c] = s1; g_S2[c] = s2; }
}

// ---------------- LN1 statistics over cat2 rows of 1024 (warp per row) ----------
__global__ void ln1stats_k() {
    int row = blockIdx.x * 8 + (threadIdx.x >> 5);
    int lane = threadIdx.x & 31;
    const float4* r = (const float4*)(g_cat2 + (size_t)row * C4);
    float s = 0.f, sq = 0.f;
#pragma unroll
    for (int i = 0; i < 8; i++) {
        float4 t = r[lane + 32 * i];
        s += t.x + t.y + t.z + t.w;
        sq += t.x * t.x + t.y * t.y + t.z * t.z + t.w * t.w;
    }
#pragma unroll
    for (int o = 16; o; o >>= 1) {
        s += __shfl_xor_sync(0xffffffffu, s, o);
        sq += __shfl_xor_sync(0xffffffffu, sq, o);
    }
    if (lane == 0) {
        float mu = s * (1.f / 1024.f);
        float var = sq * (1.f / 1024.f) - mu * mu;
        g_mu[row] = mu;
        g_rinv[row] = rsqrtf(var + 1e-5f);
    }
}

// ---------------- LN2: v = LN(u; g2, beta2), rows of 256 (warp per row) ---------
__global__ void ln2_k(const float* __restrict__ g2, const float* __restrict__ b2) {
    int row = blockIdx.x * 8 + (threadIdx.x >> 5);
    int lane = threadIdx.x & 31;
    const float* ur = g_u + (size_t)row * Cdim;
    float v[8];
    float s = 0.f, sq = 0.f;
#pragma unroll
    for (int i = 0; i < 8; i++) {
        v[i] = ur[lane + 32 * i];
        s += v[i];
        sq += v[i] * v[i];
    }
#pragma unroll
    for (int o = 16; o; o >>= 1) {
        s += __shfl_xor_sync(0xffffffffu, s, o);
        sq += __shfl_xor_sync(0xffffffffu, sq, o);
    }
    float mu = s * (1.f / 256.f);
    float var = sq * (1.f / 256.f) - mu * mu;
    float rinv = rsqrtf(var + 1e-5f);
    float* vr = g_v + (size_t)row * Cdim;
#pragma unroll
    for (int i = 0; i < 8; i++) {
        int c = lane + 32 * i;
        vr[c] = (v[i] - mu) * rinv * g2[c] + b2[c];
    }
}

// ---------------- generic tiled GEMM --------------------------------------------
// Logical: C[m][n] (+ epilogue) = sum_k a(m,k)*b(k,n)
//   a(m,k) = TA ? A[k*lda+m] : A[m*lda+k]
//   b(k,n) = TB ? B[n*ldb+k] : B[k*ldb+n]
// EPI: 0=store, 1=relu(acc+bias[n]), 2=rinv[m]*(acc-mu[m]*S1[n])+S2[n]+2*resid[m][n]
// Grid: (N/64, M/64, batches). All dims must be multiples of the tile.
template <bool TA, bool TB, int EPI>
__global__ __launch_bounds__(256)
void gemm_k(const float* __restrict__ A, int lda, long long sA,
            const float* __restrict__ B, int ldb, long long sB,
            float* __restrict__ C, int ldc, long long sC,
            int K,
            const float* __restrict__ bias,
            const float* __restrict__ resid, int ldr,
            const float* __restrict__ mu, const float* __restrict__ rinv,
            const float* __restrict__ S1, const float* __restrict__ S2) {
    __shared__ float As[16][64];
    __shared__ float Bs[16][64];
    int tid = threadIdx.x;
    int bz = blockIdx.z;
    A += (size_t)bz * sA;
    B += (size_t)bz * sB;
    C += (size_t)bz * sC;
    int bm = blockIdx.y * 64, bn = blockIdx.x * 64;
    int tx = tid & 15, ty = tid >> 4;
    float acc[4][4] = {};

    for (int k0 = 0; k0 < K; k0 += 16) {
        if (TA) {
            int m4 = (tid & 15) * 4, k = tid >> 4;
            float4 t = *(const float4*)(A + (size_t)(k0 + k) * lda + bm + m4);
            *(float4*)&As[k][m4] = t;
        } else {
#pragma unroll
            for (int i = 0; i < 4; i++) {
                int idx = i * 256 + tid;
                int k = idx & 15, m = idx >> 4;
                As[k][m] = A[(size_t)(bm + m) * lda + k0 + k];
            }
        }
        if (TB) {
#pragma unroll
            for (int i = 0; i < 4; i++) {
                int idx = i * 256 + tid;
                int k = idx & 15, n = idx >> 4;
                Bs[k][n] = B[(size_t)(bn + n) * ldb + k0 + k];
            }
        } else {
            int n4 = (tid & 15) * 4, k = tid >> 4;
            float4 t = *(const float4*)(B + (size_t)(k0 + k) * ldb + bn + n4);
            *(float4*)&Bs[k][n4] = t;
        }
        __syncthreads();
#pragma unroll
        for (int kk = 0; kk < 16; kk++) {
            float4 a4 = *(const float4*)&As[kk][ty * 4];
            float4 b4 = *(const float4*)&Bs[kk][tx * 4];
            float ar[4] = {a4.x, a4.y, a4.z, a4.w};
            float br[4] = {b4.x, b4.y, b4.z, b4.w};
#pragma unroll
            for (int i = 0; i < 4; i++)
#pragma unroll
                for (int j = 0; j < 4; j++)
                    acc[i][j] = fmaf(ar[i], br[j], acc[i][j]);
        }
        __syncthreads();
    }

    int row = bm + ty * 4, col = bn + tx * 4;
#pragma unroll
    for (int i = 0; i < 4; i++) {
        float4 o;
        float* oo = &o.x;
#pragma unroll
        for (int j = 0; j < 4; j++) {
            float val = acc[i][j];
            if (EPI == 1) val = fmaxf(val + bias[col + j], 0.f);
            if (EPI == 2) {
                float r = rinv[row + i], m_ = mu[row + i];
                val = fmaf(r, val - m_ * S1[col + j], S2[col + j]) +
                      2.f * resid[(size_t)(row + i) * ldr + col + j];
            }
            oo[j] = val;
        }
        *(float4*)(C + (size_t)(row + i) * ldc + col) = o;
    }
}

// ---------------- host launcher --------------------------------------------------
extern "C" void kernel_launch(void* const* d_in, const int* in_sizes, int n_in,
                              void* d_out, int out_size) {
    (void)in_sizes; (void)n_in; (void)out_size;
    const float* x     = (const float*)d_in[0];
    const float* Wqkv  = (const float*)d_in[1];
    const float* Wmlp  = (const float*)d_in[2];
    const float* bmlp  = (const float*)d_in[3];
    const float* g1    = (const float*)d_in[4];
    const float* beta1 = (const float*)d_in[5];
    const float* Wres  = (const float*)d_in[6];
    const float* g2    = (const float*)d_in[7];
    const float* beta2 = (const float*)d_in[8];
    float* outp = (float*)d_out;

    float *x1, *v, *sm, *u, *cat2, *ctx, *mu, *rinv, *Wg, *S1, *S2;
    cudaGetSymbolAddress((void**)&x1, g_x1);
    cudaGetSymbolAddress((void**)&v, g_v);
    cudaGetSymbolAddress((void**)&sm, g_sm);
    cudaGetSymbolAddress((void**)&u, g_u);
    cudaGetSymbolAddress((void**)&cat2, g_cat2);
    cudaGetSymbolAddress((void**)&ctx, g_ctx);
    cudaGetSymbolAddress((void**)&mu, g_mu);
    cudaGetSymbolAddress((void**)&rinv, g_rinv);
    cudaGetSymbolAddress((void**)&Wg, g_Wg);
    cudaGetSymbolAddress((void**)&S1, g_S1);
    cudaGetSymbolAddress((void**)&S2, g_S2);

    dim3 ttb(32, 8);
    // xt0 (B,N,C) from x (B,C,N); use g_u as scratch
    transpose_k<<<dim3(Ntok / 32, Cdim / 32, Bsz), ttb>>>(x, u, Cdim, Ntok);

    // x1 = xt0 @ Wqkv^T   (M=ROWS, N=256, K=256)
    gemm_k<false, true, 0><<<dim3(Cdim / 64, ROWS / 64, 1), 256>>>(
        u, Cdim, 0, Wqkv, Cdim, 0, x1, Cdim, 0, Cdim,
        nullptr, nullptr, 0, nullptr, nullptr, nullptr, nullptr);

    // v = x1
    copy_k<<<(ROWS * 64 + 255) / 256, 256>>>(v, x1, (size_t)ROWS * 64);
    // sm = softmax(x1)  (loop-invariant)
    softmax_k<<<ROWS / 8, 256>>>(x1, sm);
    // Wg, S1, S2 (loop-invariant)
    prep_k<<<Cdim / 8, 256>>>(Wres, g1, beta1);

    for (int it = 0; it < 2; ++it) {
        // cat2[:,256:512] = v
        vcopy_k<<<ROWS * 64 / 256, 256>>>();

        // ctx[b] = x1_b^T @ v_b   (M=256, N=256, K=4096, batched)
        gemm_k<true, false, 0><<<dim3(4, 4, Bsz), 256>>>(
            x1, Cdim, (long long)Ntok * Cdim, v, Cdim, (long long)Ntok * Cdim,
            ctx, Cdim, (long long)Cdim * Cdim, Ntok,
            nullptr, nullptr, 0, nullptr, nullptr, nullptr, nullptr);

        // out = sm @ ctx -> cat2[:,0:256]   (M=4096/batch, N=256, K=256, batched)
        gemm_k<false, false, 0><<<dim3(4, Ntok / 64, Bsz), 256>>>(
            sm, Cdim, (long long)Ntok * Cdim, ctx, Cdim, (long long)Cdim * Cdim,
            cat2, C4, (long long)Ntok * C4, Cdim,
            nullptr, nullptr, 0, nullptr, nullptr, nullptr, nullptr);

        // mlp = relu(cat1 @ Wmlp^T + b) -> cat2[:,512:1024]  (M=ROWS, N=512, K=512)
        gemm_k<false, true, 1><<<dim3(512 / 64, ROWS / 64, 1), 256>>>(
            cat2, C4, 0, Wmlp, 512, 0, cat2 + 512, C4, 0, 512,
            bmlp, nullptr, 0, nullptr, nullptr, nullptr, nullptr);

        // LN1 stats over cat2 rows
        ln1stats_k<<<ROWS / 8, 256>>>();

        // u = rinv*(cat2@Wg^T - mu*S1) + S2 + 2*x1   (M=ROWS, N=256, K=1024)
        gemm_k<false, true, 2><<<dim3(Cdim / 64, ROWS / 64, 1), 256>>>(
            cat2, C4, 0, Wg, C4, 0, u, Cdim, 0, C4,
            nullptr, x1, Cdim, mu, rinv, S1, S2);

        // v = LN2(u)
        ln2_k<<<ROWS / 8, 256>>>(g2, beta2);
    }

    // output (B,C,N) from v (B,N,C)
    transpose_k<<<dim3(Cdim / 32, Ntok / 32, Bsz), ttb>>>(v, outp, Ntok, Cdim);
}

// round 2
// speedup vs baseline: 5.7513x; 5.7513x over previous
#include <cuda_runtime.h>
#include <math.h>
#include <stdint.h>

#define Bsz  8
#define Cdim 256
#define Ntok 4096
#define ROWS (Bsz * Ntok)          // 32768 token rows
#define C4   (4 * Cdim)            // 1024

// ---------------- scratch (static device arrays; no allocation) ----------------
__device__ float g_x1[(size_t)ROWS * Cdim];        // x after qkv (loop-invariant)
__device__ float g_v[(size_t)ROWS * Cdim];         // v (updated per iter)
__device__ float g_sm[(size_t)ROWS * Cdim];        // softmax(x) (loop-invariant)
__device__ float g_u[(size_t)ROWS * Cdim];         // xt0 scratch, then pre-LN2 values
__device__ float g_cat2[(size_t)ROWS * C4];        // [out | v | mlp], ld=1024
__device__ float g_ctx[(size_t)Bsz * Cdim * Cdim]; // per-batch context (TRANSPOSED: ctxT[d][c])
__device__ float g_mu[ROWS];
__device__ float g_rinv[ROWS];
__device__ float g_Wg[(size_t)Cdim * C4];          // g1[k] * W_res[c,k]
__device__ float g_S1[Cdim];
__device__ float g_S2[Cdim];

// ---------------- small helpers -------------------------------------------------
__device__ __forceinline__ uint32_t cvt_tf32(float x) {
    uint32_t r;
    asm("cvt.rna.tf32.f32 %0, %1;" : "=r"(r) : "f"(x));
    return r;
}
__device__ __forceinline__ void cp16(float* s, const float* g) {
    uint32_t sa = (uint32_t)__cvta_generic_to_shared(s);
    asm volatile("cp.async.cg.shared.global [%0], [%1], 16;" :: "r"(sa), "l"(g));
}
__device__ __forceinline__ void cp_commit() { asm volatile("cp.async.commit_group;" ::); }
template <int N>
__device__ __forceinline__ void cp_wait() { asm volatile("cp.async.wait_group %0;" :: "n"(N)); }

__device__ __forceinline__ void mma8(float* c, const uint32_t* a, const uint32_t* b) {
    asm volatile(
        "mma.sync.aligned.m16n8k8.row.col.f32.tf32.tf32.f32 "
        "{%0,%1,%2,%3}, {%4,%5,%6,%7}, {%8,%9}, {%0,%1,%2,%3};"
        : "+f"(c[0]), "+f"(c[1]), "+f"(c[2]), "+f"(c[3])
        : "r"(a[0]), "r"(a[1]), "r"(a[2]), "r"(a[3]), "r"(b[0]), "r"(b[1]));
}

// stage loader: fills one (As, Bs) buffer for k-chunk starting at k0
template <bool TN>
__device__ __forceinline__ void stage_load(const float* __restrict__ A, int lda,
                                           const float* __restrict__ B, int ldb,
                                           int bm, int bn, int k0,
                                           float* as, float* bs, int tid) {
    if (!TN) {
        // As[m][k] pad 36, Bs[n][k] pad 36, Ktile=32
#pragma unroll
        for (int i = 0; i < 4; i++) {
            int idx = tid + i * 256;
            int row = idx >> 3, c4 = (idx & 7) << 2;
            cp16(as + row * 36 + c4, A + (size_t)(bm + row) * lda + k0 + c4);
            cp16(bs + row * 36 + c4, B + (size_t)(bn + row) * ldb + k0 + c4);
        }
    } else {
        // As[k][m] pad 136, Bs[k][n] pad 136
#pragma unroll
        for (int i = 0; i < 4; i++) {
            int idx = tid + i * 256;
            int row = idx >> 5, c4 = (idx & 31) << 2;
            cp16(as + row * 136 + c4, A + (size_t)(k0 + row) * lda + bm + c4);
            cp16(bs + row * 136 + c4, B + (size_t)(k0 + row) * ldb + bn + c4);
        }
    }
    cp_commit();
}

// ---------------- tf32 tensor-core GEMM ------------------------------------------
// Logical: C[m][n] = sum_k a(m,k) * b(k,n)
//   NT (TN=false): a(m,k)=A[m*lda+k], b(k,n)=B[n*ldb+k]   (both k-contiguous)
//   TN (TN=true):  a(m,k)=A[k*lda+m], b(k,n)=B[k*ldb+n]   (both k-major rows)
// EPI: 0=store, 1=relu(acc+bias[n]), 2=rinv[m]*(acc-mu[m]*S1[n])+S2[n]+2*resid, 3=atomicAdd
// CTA tile 128x128, Ktile 32, 8 warps (2x4), warp tile 64x32, m16n8k8 tf32.
template <bool TN, int EPI, int SPLITK>
__global__ __launch_bounds__(256, 2)
void gemm_tc(const float* __restrict__ A, int lda, long long sA,
             const float* __restrict__ B, int ldb, long long sB,
             float* __restrict__ C, int ldc, long long sC, int K,
             const float* __restrict__ bias,
             const float* __restrict__ resid, int ldr,
             const float* __restrict__ mu, const float* __restrict__ rinv,
             const float* __restrict__ S1, const float* __restrict__ S2) {
    extern __shared__ float smem[];
    constexpr int ABUF = TN ? 32 * 136 : 128 * 36;
    float* As = smem;
    float* Bs = smem + 2 * ABUF;

    int bz = blockIdx.z;
    int batch = bz / SPLITK, ks = bz - batch * SPLITK;
    A += (size_t)batch * sA;
    B += (size_t)batch * sB;
    C += (size_t)batch * sC;
    const int kchunk = K / SPLITK;
    const int kbase = ks * kchunk;
    const int bm = blockIdx.y * 128, bn = blockIdx.x * 128;
    const int tid = threadIdx.x;
    const int wid = tid >> 5, lane = tid & 31;
    const int wm = (wid >> 2) * 64, wn = (wid & 3) * 32;
    const int lq = lane >> 2, lr = lane & 3;

    float acc[4][4][4];
#pragma unroll
    for (int i = 0; i < 4; i++)
#pragma unroll
        for (int j = 0; j < 4; j++)
#pragma unroll
            for (int t = 0; t < 4; t++) acc[i][j][t] = 0.f;

    const int KT = kchunk / 32;

    stage_load<TN>(A, lda, B, ldb, bm, bn, kbase, As, Bs, tid);

    for (int kt = 0; kt < KT; kt++) {
        int buf = kt & 1;
        if (kt + 1 < KT) {
            stage_load<TN>(A, lda, B, ldb, bm, bn, kbase + (kt + 1) * 32,
                           As + ((kt + 1) & 1) * ABUF, Bs + ((kt + 1) & 1) * ABUF, tid);
            cp_wait<1>();
        } else {
            cp_wait<0>();
        }
        __syncthreads();
        const float* as = As + buf * ABUF;
        const float* bs = Bs + buf * ABUF;
#pragma unroll
        for (int kk = 0; kk < 4; kk++) {
            const int k0 = kk * 8;
            uint32_t af[4][4], bf[4][2];
            if (!TN) {
#pragma unroll
                for (int i = 0; i < 4; i++) {
                    const float* p = as + (wm + i * 16 + lq) * 36 + k0 + lr;
                    af[i][0] = cvt_tf32(p[0]);
                    af[i][2] = cvt_tf32(p[4]);
                    const float* p8 = p + 8 * 36;
                    af[i][1] = cvt_tf32(p8[0]);
                    af[i][3] = cvt_tf32(p8[4]);
                }
#pragma unroll
                for (int j = 0; j < 4; j++) {
                    const float* p = bs + (wn + j * 8 + lq) * 36 + k0 + lr;
                    bf[j][0] = cvt_tf32(p[0]);
                    bf[j][1] = cvt_tf32(p[4]);
                }
            } else {
#pragma unroll
                for (int i = 0; i < 4; i++) {
                    const float* p = as + (k0 + lr) * 136 + wm + i * 16 + lq;
                    af[i][0] = cvt_tf32(p[0]);
                    af[i][1] = cvt_tf32(p[8]);
                    const float* p4 = p + 4 * 136;
                    af[i][2] = cvt_tf32(p4[0]);
                    af[i][3] = cvt_tf32(p4[8]);
                }
#pragma unroll
                for (int j = 0; j < 4; j++) {
                    const float* p = bs + (k0 + lr) * 136 + wn + j * 8 + lq;
                    bf[j][0] = cvt_tf32(p[0]);
                    bf[j][1] = cvt_tf32(p[4 * 136]);
                }
            }
#pragma unroll
            for (int i = 0; i < 4; i++)
#pragma unroll
                for (int j = 0; j < 4; j++) mma8(acc[i][j], af[i], bf[j]);
        }
        __syncthreads();
    }

    // epilogue
#pragma unroll
    for (int i = 0; i < 4; i++) {
#pragma unroll
        for (int j = 0; j < 4; j++) {
            int c = bn + wn + j * 8 + lr * 2;
#pragma unroll
            for (int rr = 0; rr < 2; rr++) {
                int row = bm + wm + i * 16 + lq + rr * 8;
                float v0 = acc[i][j][rr * 2 + 0], v1 = acc[i][j][rr * 2 + 1];
                if (EPI == 1) {
                    v0 = fmaxf(v0 + bias[c], 0.f);
                    v1 = fmaxf(v1 + bias[c + 1], 0.f);
                }
                if (EPI == 2) {
                    float rv = rinv[row], m_ = mu[row];
                    const float* rp = resid + (size_t)row * ldr + c;
                    v0 = fmaf(rv, v0 - m_ * S1[c], S2[c]) + 2.f * rp[0];
                    v1 = fmaf(rv, v1 - m_ * S1[c + 1], S2[c + 1]) + 2.f * rp[1];
                }
                if (EPI == 3) {
                    atomicAdd(C + (size_t)row * ldc + c, v0);
                    atomicAdd(C + (size_t)row * ldc + c + 1, v1);
                } else {
                    *(float2*)(C + (size_t)row * ldc + c) = make_float2(v0, v1);
                }
            }
        }
    }
}

// ---------------- tiled transpose: in (R x Cc) -> out (Cc x R), batched in z ----
__global__ void transpose_k(const float* __restrict__ in, float* __restrict__ out,
                            int R, int Cc) {
    __shared__ float tile[32][33];
    size_t base = (size_t)blockIdx.z * R * Cc;
    in += base; out += base;
    int c0 = blockIdx.x * 32, r0 = blockIdx.y * 32;
    int tx = threadIdx.x, ty = threadIdx.y;  // 32x8
#pragma unroll
    for (int j = 0; j < 32; j += 8)
        tile[ty + j][tx] = in[(size_t)(r0 + ty + j) * Cc + c0 + tx];
    __syncthreads();
#pragma unroll
    for (int j = 0; j < 32; j += 8)
        out[(size_t)(c0 + ty + j) * R + r0 + tx] = tile[tx][ty + j];
}

// ---------------- softmax over rows of 256 (one warp per row) ------------------
__global__ void softmax_k(const float* __restrict__ x, float* __restrict__ y) {
    int row = blockIdx.x * 8 + (threadIdx.x >> 5);
    int lane = threadIdx.x & 31;
    const float* xr = x + (size_t)row * Cdim;
    float v[8];
    float mx = -1e30f;
#pragma unroll
    for (int i = 0; i < 8; i++) { v[i] = xr[lane + 32 * i]; mx = fmaxf(mx, v[i]); }
#pragma unroll
    for (int o = 16; o; o >>= 1) mx = fmaxf(mx, __shfl_xor_sync(0xffffffffu, mx, o));
    float s = 0.f;
#pragma unroll
    for (int i = 0; i < 8; i++) { v[i] = __expf(v[i] - mx); s += v[i]; }
#pragma unroll
    for (int o = 16; o; o >>= 1) s += __shfl_xor_sync(0xffffffffu, s, o);
    float inv = 1.f / s;
    float* yr = y + (size_t)row * Cdim;
#pragma unroll
    for (int i = 0; i < 8; i++) yr[lane + 32 * i] = v[i] * inv;
}

// ---------------- simple float4 copy / zero -------------------------------------
__global__ void copy_k(float* __restrict__ dst, const float* __restrict__ src, size_t n4) {
    size_t i = (size_t)blockIdx.x * blockDim.x + threadIdx.x;
    if (i < n4) ((float4*)dst)[i] = ((const float4*)src)[i];
}
__global__ void zero_k(float* __restrict__ p, size_t n4) {
    size_t i = (size_t)blockIdx.x * blockDim.x + threadIdx.x;
    if (i < n4) ((float4*)p)[i] = make_float4(0.f, 0.f, 0.f, 0.f);
}

// ---------------- copy v into cat2 columns [256,512) ----------------------------
__global__ void vcopy_k() {
    int i = blockIdx.x * 256 + threadIdx.x;     // over ROWS*64 float4s
    int m = i >> 6, c = i & 63;
    ((float4*)g_cat2)[(size_t)m * 256 + 64 + c] = ((const float4*)g_v)[(size_t)m * 64 + c];
}

// ---------------- precompute Wg = g1*W_res, S1, S2 (one warp per output c) ------
__global__ void prep_k(const float* __restrict__ Wres, const float* __restrict__ g1,
                       const float* __restrict__ beta1) {
    int c = blockIdx.x * 8 + (threadIdx.x >> 5);
    int lane = threadIdx.x & 31;
    const float* wr = Wres + (size_t)c * C4;
    float s1 = 0.f, s2 = 0.f;
    for (int k = lane; k < C4; k += 32) {
        float w = wr[k], g = g1[k];
        g_Wg[(size_t)c * C4 + k] = g * w;
        s1 += g * w;
        s2 += beta1[k] * w;
    }
#pragma unroll
    for (int o = 16; o; o >>= 1) {
        s1 += __shfl_xor_sync(0xffffffffu, s1, o);
        s2 += __shfl_xor_sync(0xffffffffu, s2, o);
    }
    if (lane == 0) { g_S1[c] = s1; g_S2[c] = s2; }
}

// ---------------- LN1 statistics over cat2 rows of 1024 (warp per row) ----------
__global__ void ln1stats_k() {
    int row = blockIdx.x * 8 + (threadIdx.x >> 5);
    int lane = threadIdx.x & 31;
    const float4* r = (const float4*)(g_cat2 + (size_t)row * C4);
    float s = 0.f, sq = 0.f;
#pragma unroll
    for (int i = 0; i < 8; i++) {
        float4 t = r[lane + 32 * i];
        s += t.x + t.y + t.z + t.w;
        sq += t.x * t.x + t.y * t.y + t.z * t.z + t.w * t.w;
    }
#pragma unroll
    for (int o = 16; o; o >>= 1) {
        s += __shfl_xor_sync(0xffffffffu, s, o);
        sq += __shfl_xor_sync(0xffffffffu, sq, o);
    }
    if (lane == 0) {
        float mu = s * (1.f / 1024.f);
        float var = sq * (1.f / 1024.f) - mu * mu;
        g_mu[row] = mu;
        g_rinv[row] = rsqrtf(var + 1e-5f);
    }
}

// ---------------- LN2: v = LN(u; g2, beta2), rows of 256 (warp per row) ---------
__global__ void ln2_k(const float* __restrict__ g2, const float* __restrict__ b2) {
    int row = blockIdx.x * 8 + (threadIdx.x >> 5);
    int lane = threadIdx.x & 31;
    const float* ur = g_u + (size_t)row * Cdim;
    float v[8];
    float s = 0.f, sq = 0.f;
#pragma unroll
    for (int i = 0; i < 8; i++) {
        v[i] = ur[lane + 32 * i];
        s += v[i];
        sq += v[i] * v[i];
    }
#pragma unroll
    for (int o = 16; o; o >>= 1) {
        s += __shfl_xor_sync(0xffffffffu, s, o);
        sq += __shfl_xor_sync(0xffffffffu, sq, o);
    }
    float mu = s * (1.f / 256.f);
    float var = sq * (1.f / 256.f) - mu * mu;
    float rinv = rsqrtf(var + 1e-5f);
    float* vr = g_v + (size_t)row * Cdim;
#pragma unroll
    for (int i = 0; i < 8; i++) {
        int c = lane + 32 * i;
        vr[c] = (v[i] - mu) * rinv * g2[c] + b2[c];
    }
}

// ---------------- host launcher --------------------------------------------------
extern "C" void kernel_launch(void* const* d_in, const int* in_sizes, int n_in,
                              void* d_out, int out_size) {
    (void)in_sizes; (void)n_in; (void)out_size;
    const float* x     = (const float*)d_in[0];
    const float* Wqkv  = (const float*)d_in[1];
    const float* Wmlp  = (const float*)d_in[2];
    const float* bmlp  = (const float*)d_in[3];
    const float* g1    = (const float*)d_in[4];
    const float* beta1 = (const float*)d_in[5];
    const float* Wres  = (const float*)d_in[6];
    const float* g2    = (const float*)d_in[7];
    const float* beta2 = (const float*)d_in[8];
    float* outp = (float*)d_out;

    float *x1, *v, *sm, *u, *cat2, *ctx, *mu, *rinv, *Wg, *S1, *S2;
    cudaGetSymbolAddress((void**)&x1, g_x1);
    cudaGetSymbolAddress((void**)&v, g_v);
    cudaGetSymbolAddress((void**)&sm, g_sm);
    cudaGetSymbolAddress((void**)&u, g_u);
    cudaGetSymbolAddress((void**)&cat2, g_cat2);
    cudaGetSymbolAddress((void**)&ctx, g_ctx);
    cudaGetSymbolAddress((void**)&mu, g_mu);
    cudaGetSymbolAddress((void**)&rinv, g_rinv);
    cudaGetSymbolAddress((void**)&Wg, g_Wg);
    cudaGetSymbolAddress((void**)&S1, g_S1);
    cudaGetSymbolAddress((void**)&S2, g_S2);

    const int smemNT = 4 * 128 * 36 * 4;   // 73728 B
    const int smemTN = 4 * 32 * 136 * 4;   // 69632 B
    cudaFuncSetAttribute(gemm_tc<false, 0, 1>, cudaFuncAttributeMaxDynamicSharedMemorySize, smemNT);
    cudaFuncSetAttribute(gemm_tc<false, 1, 1>, cudaFuncAttributeMaxDynamicSharedMemorySize, smemNT);
    cudaFuncSetAttribute(gemm_tc<false, 2, 1>, cudaFuncAttributeMaxDynamicSharedMemorySize, smemNT);
    cudaFuncSetAttribute(gemm_tc<true, 3, 8>, cudaFuncAttributeMaxDynamicSharedMemorySize, smemTN);

    dim3 ttb(32, 8);
    // xt0 (B,N,C) from x (B,C,N); use g_u as scratch
    transpose_k<<<dim3(Ntok / 32, Cdim / 32, Bsz), ttb>>>(x, u, Cdim, Ntok);

    // x1 = xt0 @ Wqkv^T   (NT: M=ROWS, N=256, K=256)
    gemm_tc<false, 0, 1><<<dim3(2, ROWS / 128, 1), 256, smemNT>>>(
        u, Cdim, 0, Wqkv, Cdim, 0, x1, Cdim, 0, Cdim,
        nullptr, nullptr, 0, nullptr, nullptr, nullptr, nullptr);

    // v = x1
    copy_k<<<(ROWS * 64 + 255) / 256, 256>>>(v, x1, (size_t)ROWS * 64);
    // sm = softmax(x1)  (loop-invariant)
    softmax_k<<<ROWS / 8, 256>>>(x1, sm);
    // Wg, S1, S2 (loop-invariant)
    prep_k<<<Cdim / 8, 256>>>(Wres, g1, beta1);

    for (int it = 0; it < 2; ++it) {
        // cat2[:,256:512] = v
        vcopy_k<<<ROWS * 64 / 256, 256>>>();

        // ctxT[d][c] = sum_n v[n][d] * x1[n][c]  (TN, split-K 8, atomic accumulate)
        zero_k<<<(Bsz * Cdim * Cdim / 4 + 255) / 256, 256>>>(ctx, (size_t)Bsz * Cdim * Cdim / 4);
        gemm_tc<true, 3, 8><<<dim3(2, 2, Bsz * 8), 256, smemTN>>>(
            v, Cdim, (long long)Ntok * Cdim, x1, Cdim, (long long)Ntok * Cdim,
            ctx, Cdim, (long long)Cdim * Cdim, Ntok,
            nullptr, nullptr, 0, nullptr, nullptr, nullptr, nullptr);

        // out = sm @ ctx  == NT with B = ctxT  -> cat2[:,0:256]
        gemm_tc<false, 0, 1><<<dim3(2, Ntok / 128, Bsz), 256, smemNT>>>(
            sm, Cdim, (long long)Ntok * Cdim, ctx, Cdim, (long long)Cdim * Cdim,
            cat2, C4, (long long)Ntok * C4, Cdim,
            nullptr, nullptr, 0, nullptr, nullptr, nullptr, nullptr);

        // mlp = relu(cat1 @ Wmlp^T + b) -> cat2[:,512:1024]  (NT: M=ROWS, N=512, K=512)
        gemm_tc<false, 1, 1><<<dim3(4, ROWS / 128, 1), 256, smemNT>>>(
            cat2, C4, 0, Wmlp, 512, 0, cat2 + 512, C4, 0, 512,
            bmlp, nullptr, 0, nullptr, nullptr, nullptr, nullptr);

        // LN1 stats over cat2 rows
        ln1stats_k<<<ROWS / 8, 256>>>();

        // u = rinv*(cat2@Wg^T - mu*S1) + S2 + 2*x1   (NT: M=ROWS, N=256, K=1024)
        gemm_tc<false, 2, 1><<<dim3(2, ROWS / 128, 1), 256, smemNT>>>(
            cat2, C4, 0, Wg, C4, 0, u, Cdim, 0, C4,
            nullptr, x1, Cdim, mu, rinv, S1, S2);

        // v = LN2(u)
        ln2_k<<<ROWS / 8, 256>>>(g2, beta2);
    }

    // output (B,C,N) from v (B,N,C)
    transpose_k<<<dim3(Cdim / 32, Ntok / 32, Bsz), ttb>>>(v, outp, Ntok, Cdim);
}

// round 4
// speedup vs baseline: 8.7367x; 1.5191x over previous
#include <cuda_runtime.h>
#include <math.h>
#include <stdint.h>

#define Bsz  8
#define Cdim 256
#define Ntok 4096
#define ROWS (Bsz * Ntok)          // 32768 token rows
#define C4   (4 * Cdim)            // 1024

// ---------------- scratch (static device arrays; no allocation) ----------------
__device__ float g_x1[(size_t)ROWS * Cdim];
__device__ float g_v[(size_t)ROWS * Cdim];
__device__ float g_sm[(size_t)ROWS * Cdim];
__device__ float g_u[(size_t)ROWS * Cdim];
__device__ float g_cat2[(size_t)ROWS * C4];        // [out | v | mlp], ld=1024
__device__ float g_ctx[(size_t)Bsz * Cdim * Cdim]; // ctxT[d][c]
__device__ float g_mu[ROWS];
__device__ float g_rinv[ROWS];
__device__ float g_Wg[(size_t)Cdim * C4];
__device__ float g_S1[Cdim];
__device__ float g_S2[Cdim];

// Accelerated tcgen05 available only on arch-specific ('a') targets.
#if defined(__CUDA_ARCH_FEAT_SM103_ALL) || defined(__CUDA_ARCH_FEAT_SM100_ALL)
#define HAS_TCGEN05 1
#else
#define HAS_TCGEN05 0
#endif

// ================= helpers ======================================================
__device__ __forceinline__ uint32_t smem_u32(const void* p) {
    return (uint32_t)__cvta_generic_to_shared(p);
}
__device__ __forceinline__ uint32_t elect1() {
    uint32_t pred;
    asm volatile("{\n\t.reg .pred p;\n\telect.sync _|p, 0xFFFFFFFF;\n\tselp.b32 %0, 1, 0, p;\n\t}"
                 : "=r"(pred));
    return pred;
}
__device__ __forceinline__ void mbar_init(uint32_t a, uint32_t cnt) {
    asm volatile("mbarrier.init.shared.b64 [%0], %1;" :: "r"(a), "r"(cnt) : "memory");
}
__device__ __forceinline__ void mbar_wait(uint32_t a, int ph) {
    asm volatile(
        "{\n\t.reg .pred P;\n\t"
        "WL%=:\n\t"
        "mbarrier.try_wait.parity.acquire.cta.shared::cta.b64 P, [%0], %1, 0x989680;\n\t"
        "@P bra.uni WD%=;\n\t"
        "bra.uni WL%=;\n\t"
        "WD%=:\n\t}"
        :: "r"(a), "r"(ph) : "memory");
}
#define SW128B(o) ((o) ^ (((o) >> 3) & 0x70))

static constexpr unsigned long long DESC_SW128 =
    (2ull << 61) | (1ull << 46) | (64ull << 32) | (1ull << 16);
__device__ __forceinline__ uint64_t mk_desc(uint32_t addr) {
    return DESC_SW128 | ((uint64_t)(addr >> 4) & 0x3FFF);
}

__device__ __forceinline__ uint32_t cvt_tf32(float x) {
    uint32_t r;
    asm("cvt.rna.tf32.f32 %0, %1;" : "=r"(r) : "f"(x));
    return r;
}
__device__ __forceinline__ void cp16(float* s, const float* g) {
    uint32_t sa = smem_u32(s);
    asm volatile("cp.async.cg.shared.global [%0], [%1], 16;" :: "r"(sa), "l"(g));
}
__device__ __forceinline__ void cp16s(uint32_t sa, const float* g) {
    asm volatile("cp.async.cg.shared.global [%0], [%1], 16;" :: "r"(sa), "l"(g));
}
__device__ __forceinline__ void cp_commit() { asm volatile("cp.async.commit_group;" ::); }
template <int N>
__device__ __forceinline__ void cp_wait() { asm volatile("cp.async.wait_group %0;" :: "n"(N)); }

__device__ __forceinline__ void mma8(float* c, const uint32_t* a, const uint32_t* b) {
    asm volatile(
        "mma.sync.aligned.m16n8k8.row.col.f32.tf32.tf32.f32 "
        "{%0,%1,%2,%3}, {%4,%5,%6,%7}, {%8,%9}, {%0,%1,%2,%3};"
        : "+f"(c[0]), "+f"(c[1]), "+f"(c[2]), "+f"(c[3])
        : "r"(a[0]), "r"(a[1]), "r"(a[2]), "r"(a[3]), "r"(b[0]), "r"(b[1]));
}

// ================= unified NT GEMM ==============================================
// C[m][n] = sum_k A[m*lda+k] * B[n*ldb+k], CTA tile 128x128, K-tile 32, 256 thr.
// EPI: 0=store, 1=relu(acc+bias[n]), 2=rinv[m]*(acc-mu[m]*S1[n])+S2[n]+2*resid
// Dynamic smem: 73728 B (covers both branch layouts).
#define T5_SMEM 73728

#if HAS_TCGEN05
// swizzled SW128 staging for tcgen05, 256 threads
__device__ __forceinline__ void tc_stage(const float* __restrict__ A, int lda,
                                         const float* __restrict__ B, int ldb,
                                         int bm, int bn, int k0,
                                         char* smem, int sbase, int tid) {
#pragma unroll
    for (int i = 0; i < 4; i++) {
        int c = tid + i * 256;
        int row = c >> 3, in16 = c & 7;
        uint32_t so = SW128B((uint32_t)(row * 128 + in16 * 16));
        cp16s(smem_u32(smem + sbase + so), A + (size_t)(bm + row) * lda + k0 + in16 * 4);
    }
#pragma unroll
    for (int i = 0; i < 4; i++) {
        int c = tid + i * 256;
        int row = c >> 3, in16 = c & 7;
        uint32_t so = SW128B((uint32_t)(row * 128 + in16 * 16));
        cp16s(smem_u32(smem + sbase + 16384 + so), B + (size_t)(bn + row) * ldb + k0 + in16 * 4);
    }
    cp_commit();
}
#endif

// unswizzled NT staging for legacy fallback, 256 threads
__device__ __forceinline__ void nt_stage(const float* __restrict__ A, int lda,
                                         const float* __restrict__ B, int ldb,
                                         int bm, int bn, int k0,
                                         float* as, float* bs, int tid) {
#pragma unroll
    for (int i = 0; i < 4; i++) {
        int idx = tid + i * 256;
        int row = idx >> 3, c4 = (idx & 7) << 2;
        cp16(as + row * 36 + c4, A + (size_t)(bm + row) * lda + k0 + c4);
        cp16(bs + row * 36 + c4, B + (size_t)(bn + row) * ldb + k0 + c4);
    }
    cp_commit();
}

template <int EPI>
__global__ __launch_bounds__(256)
void gemm_t5(const float* __restrict__ A, int lda, long long sA,
             const float* __restrict__ B, int ldb, long long sB,
             float* __restrict__ C, int ldc, long long sC, int K,
             const float* __restrict__ bias,
             const float* __restrict__ resid, int ldr,
             const float* __restrict__ mu, const float* __restrict__ rinv,
             const float* __restrict__ S1, const float* __restrict__ S2) {
    extern __shared__ char smem[];
    const int tid = threadIdx.x, wid = tid >> 5, lane = tid & 31;
    const int bz = blockIdx.z;
    A += (size_t)bz * sA;
    B += (size_t)bz * sB;
    C += (size_t)bz * sC;
    const int bm = blockIdx.y * 128, bn = blockIdx.x * 128;

#if HAS_TCGEN05
    // ---------------- tcgen05 tf32 SS path ----------------
    uint32_t sb = smem_u32(smem);
    if (wid == 0) {
        asm volatile("tcgen05.alloc.cta_group::1.sync.aligned.shared::cta.b32 [%0], %1;"
                     :: "r"(sb), "r"(128) : "memory");
        asm volatile("tcgen05.relinquish_alloc_permit.cta_group::1.sync.aligned;");
    }
    if (tid == 0) { mbar_init(sb + 8, 1); mbar_init(sb + 16, 1); }
    __syncthreads();
    uint32_t tmem;
    asm volatile("ld.shared.b32 %0, [%1];" : "=r"(tmem) : "r"(sb));

    const int KT = K / 32;
    tc_stage(A, lda, B, ldb, bm, bn, 0, smem, 1024, tid);
    tc_stage(A, lda, B, ldb, bm, bn, 32, smem, 1024 + 32768, tid);
    int ph0 = 0, ph1 = 0;
    // idesc: dtype=F32(1)<<4, atype=TF32(2)<<7, btype=TF32(2)<<10, N/8<<17, M/16<<24
    const uint32_t IDESC = (1u << 4) | (2u << 7) | (2u << 10) | (16u << 17) | (8u << 24);

    for (int kt = 0; kt < KT; kt++) {
        int buf = kt & 1;
        if (kt == KT - 1) cp_wait<0>(); else cp_wait<1>();
        asm volatile("fence.proxy.async.shared::cta;" ::: "memory");
        __syncthreads();
        if (wid == 0 && elect1()) {
            uint64_t ad = mk_desc(sb + 1024 + buf * 32768);
            uint64_t bd = mk_desc(sb + 1024 + buf * 32768 + 16384);
#pragma unroll
            for (int s = 0; s < 4; s++) {
                uint32_t en = (kt > 0 || s > 0) ? 1u : 0u;
                asm volatile(
                    "{\n\t.reg .pred p;\n\tsetp.ne.u32 p, %5, 0;\n\t"
                    "tcgen05.mma.cta_group::1.kind::tf32 [%0], %1, %2, %3, {%4,%4,%4,%4}, p;\n\t}"
                    :: "r"(tmem), "l"(ad + s * 2), "l"(bd + s * 2), "r"(IDESC),
                       "r"(0u), "r"(en) : "memory");
            }
            asm volatile(
                "tcgen05.commit.cta_group::1.mbarrier::arrive::one.shared::cluster.b64 [%0];"
                :: "r"(sb + 8 + buf * 8) : "memory");
        }
        if (kt + 2 < KT) {
            if (buf == 0) { mbar_wait(sb + 8, ph0); ph0 ^= 1; }
            else          { mbar_wait(sb + 16, ph1); ph1 ^= 1; }
            tc_stage(A, lda, B, ldb, bm, bn, (kt + 2) * 32, smem, 1024 + buf * 32768, tid);
        }
    }
    int lb = (KT - 1) & 1;
    if (lb == 0) mbar_wait(sb + 8, ph0); else mbar_wait(sb + 16, ph1);
    asm volatile("tcgen05.fence::after_thread_sync;" ::: "memory");

    // epilogue: warp w -> rows bm+(w&3)*32+lane, column half (w>>2)*64
    const int row = bm + (wid & 3) * 32 + lane;
    const int cb = (wid >> 2) * 64;
    float rv = 0.f, mm = 0.f;
    if (EPI == 2) { rv = rinv[row]; mm = mu[row]; }
#pragma unroll
    for (int cc = 0; cc < 2; cc++) {
        int c0 = cb + cc * 32;
        uint32_t d[32];
        asm volatile(
            "tcgen05.ld.sync.aligned.32x32b.x32.b32 "
            "{%0, %1, %2, %3, %4, %5, %6, %7, "
            " %8, %9, %10, %11, %12, %13, %14, %15, "
            " %16, %17, %18, %19, %20, %21, %22, %23, "
            " %24, %25, %26, %27, %28, %29, %30, %31}, [%32];"
            : "=r"(d[0]), "=r"(d[1]), "=r"(d[2]), "=r"(d[3]),
              "=r"(d[4]), "=r"(d[5]), "=r"(d[6]), "=r"(d[7]),
              "=r"(d[8]), "=r"(d[9]), "=r"(d[10]), "=r"(d[11]),
              "=r"(d[12]), "=r"(d[13]), "=r"(d[14]), "=r"(d[15]),
              "=r"(d[16]), "=r"(d[17]), "=r"(d[18]), "=r"(d[19]),
              "=r"(d[20]), "=r"(d[21]), "=r"(d[22]), "=r"(d[23]),
              "=r"(d[24]), "=r"(d[25]), "=r"(d[26]), "=r"(d[27]),
              "=r"(d[28]), "=r"(d[29]), "=r"(d[30]), "=r"(d[31])
            : "r"(tmem + c0));
        asm volatile("tcgen05.wait::ld.sync.aligned;" ::: "memory");
#pragma unroll
        for (int j = 0; j < 32; j += 4) {
            int c = bn + c0 + j;
            float4 o;
            float* ov = &o.x;
#pragma unroll
            for (int q = 0; q < 4; q++) {
                float val = __uint_as_float(d[j + q]);
                if (EPI == 1) val = fmaxf(val + bias[c + q], 0.f);
                if (EPI == 2) val = fmaf(rv, val - mm * S1[c + q], S2[c + q]);
                ov[q] = val;
            }
            if (EPI == 2) {
                const float4 rp = *(const float4*)(resid + (size_t)row * ldr + c);
                o.x += 2.f * rp.x; o.y += 2.f * rp.y;
                o.z += 2.f * rp.z; o.w += 2.f * rp.w;
            }
            *(float4*)(C + (size_t)row * ldc + c) = o;
        }
    }
    __syncthreads();
    if (wid == 0) {
        asm volatile("tcgen05.dealloc.cta_group::1.sync.aligned.b32 %0, %1;"
                     :: "r"(tmem), "r"(128));
    }
#else
    // ---------------- legacy tf32 warp-MMA fallback (proven round-2 path) -------
    float* fsm = (float*)smem;
    constexpr int ABUF = 128 * 36;
    float* As = fsm;
    float* Bs = fsm + 2 * ABUF;
    const int wm = (wid >> 2) * 64, wn = (wid & 3) * 32;
    const int lq = lane >> 2, lr = lane & 3;
    float acc[4][4][4];
#pragma unroll
    for (int i = 0; i < 4; i++)
#pragma unroll
        for (int j = 0; j < 4; j++)
#pragma unroll
            for (int t = 0; t < 4; t++) acc[i][j][t] = 0.f;
    const int KT = K / 32;
    nt_stage(A, lda, B, ldb, bm, bn, 0, As, Bs, tid);
    for (int kt = 0; kt < KT; kt++) {
        int buf = kt & 1;
        if (kt + 1 < KT) {
            nt_stage(A, lda, B, ldb, bm, bn, (kt + 1) * 32,
                     As + ((kt + 1) & 1) * ABUF, Bs + ((kt + 1) & 1) * ABUF, tid);
            cp_wait<1>();
        } else cp_wait<0>();
        __syncthreads();
        const float* as = As + buf * ABUF;
        const float* bs = Bs + buf * ABUF;
#pragma unroll
        for (int kk = 0; kk < 4; kk++) {
            const int k0 = kk * 8;
            uint32_t af[4][4], bf[4][2];
#pragma unroll
            for (int i = 0; i < 4; i++) {
                const float* p = as + (wm + i * 16 + lq) * 36 + k0 + lr;
                af[i][0] = cvt_tf32(p[0]);
                af[i][2] = cvt_tf32(p[4]);
                const float* p8 = p + 8 * 36;
                af[i][1] = cvt_tf32(p8[0]);
                af[i][3] = cvt_tf32(p8[4]);
            }
#pragma unroll
            for (int j = 0; j < 4; j++) {
                const float* p = bs + (wn + j * 8 + lq) * 36 + k0 + lr;
                bf[j][0] = cvt_tf32(p[0]);
                bf[j][1] = cvt_tf32(p[4]);
            }
#pragma unroll
            for (int i = 0; i < 4; i++)
#pragma unroll
                for (int j = 0; j < 4; j++) mma8(acc[i][j], af[i], bf[j]);
        }
        __syncthreads();
    }
#pragma unroll
    for (int i = 0; i < 4; i++) {
#pragma unroll
        for (int j = 0; j < 4; j++) {
            int c = bn + wn + j * 8 + lr * 2;
#pragma unroll
            for (int rr = 0; rr < 2; rr++) {
                int row = bm + wm + i * 16 + lq + rr * 8;
                float v0 = acc[i][j][rr * 2 + 0], v1 = acc[i][j][rr * 2 + 1];
                if (EPI == 1) {
                    v0 = fmaxf(v0 + bias[c], 0.f);
                    v1 = fmaxf(v1 + bias[c + 1], 0.f);
                }
                if (EPI == 2) {
                    float rv = rinv[row], m_ = mu[row];
                    const float* rp = resid + (size_t)row * ldr + c;
                    v0 = fmaf(rv, v0 - m_ * S1[c], S2[c]) + 2.f * rp[0];
                    v1 = fmaf(rv, v1 - m_ * S1[c + 1], S2[c + 1]) + 2.f * rp[1];
                }
                *(float2*)(C + (size_t)row * ldc + c) = make_float2(v0, v1);
            }
        }
    }
#endif
}

// ================= legacy tf32 warp-MMA GEMM (TN, split-K, atomic) =============
__device__ __forceinline__ void stage_tn(const float* __restrict__ A, int lda,
                                         const float* __restrict__ B, int ldb,
                                         int bm, int bn, int k0,
                                         float* as, float* bs, int tid) {
#pragma unroll
    for (int i = 0; i < 4; i++) {
        int idx = tid + i * 256;
        int row = idx >> 5, c4 = (idx & 31) << 2;
        cp16(as + row * 136 + c4, A + (size_t)(k0 + row) * lda + bm + c4);
        cp16(bs + row * 136 + c4, B + (size_t)(k0 + row) * ldb + bn + c4);
    }
    cp_commit();
}
template <int SPLITK>
__global__ __launch_bounds__(256, 2)
void gemm_tn(const float* __restrict__ A, int lda, long long sA,
             const float* __restrict__ B, int ldb, long long sB,
             float* __restrict__ C, int ldc, long long sC, int K) {
    extern __shared__ float fsm[];
    constexpr int ABUF = 32 * 136;
    float* As = fsm;
    float* Bs = fsm + 2 * ABUF;
    int bz = blockIdx.z;
    int batch = bz / SPLITK, ks = bz - batch * SPLITK;
    A += (size_t)batch * sA;
    B += (size_t)batch * sB;
    C += (size_t)batch * sC;
    const int kchunk = K / SPLITK, kbase = ks * kchunk;
    const int bm = blockIdx.y * 128, bn = blockIdx.x * 128;
    const int tid = threadIdx.x, wid = tid >> 5, lane = tid & 31;
    const int wm = (wid >> 2) * 64, wn = (wid & 3) * 32;
    const int lq = lane >> 2, lr = lane & 3;
    float acc[4][4][4];
#pragma unroll
    for (int i = 0; i < 4; i++)
#pragma unroll
        for (int j = 0; j < 4; j++)
#pragma unroll
            for (int t = 0; t < 4; t++) acc[i][j][t] = 0.f;
    const int KT = kchunk / 32;
    stage_tn(A, lda, B, ldb, bm, bn, kbase, As, Bs, tid);
    for (int kt = 0; kt < KT; kt++) {
        int buf = kt & 1;
        if (kt + 1 < KT) {
            stage_tn(A, lda, B, ldb, bm, bn, kbase + (kt + 1) * 32,
                     As + ((kt + 1) & 1) * ABUF, Bs + ((kt + 1) & 1) * ABUF, tid);
            cp_wait<1>();
        } else cp_wait<0>();
        __syncthreads();
        const float* as = As + buf * ABUF;
        const float* bs = Bs + buf * ABUF;
#pragma unroll
        for (int kk = 0; kk < 4; kk++) {
            const int k0 = kk * 8;
            uint32_t af[4][4], bf[4][2];
#pragma unroll
            for (int i = 0; i < 4; i++) {
                const float* p = as + (k0 + lr) * 136 + wm + i * 16 + lq;
                af[i][0] = cvt_tf32(p[0]);
                af[i][1] = cvt_tf32(p[8]);
                const float* p4 = p + 4 * 136;
                af[i][2] = cvt_tf32(p4[0]);
                af[i][3] = cvt_tf32(p4[8]);
            }
#pragma unroll
            for (int j = 0; j < 4; j++) {
                const float* p = bs + (k0 + lr) * 136 + wn + j * 8 + lq;
                bf[j][0] = cvt_tf32(p[0]);
                bf[j][1] = cvt_tf32(p[4 * 136]);
            }
#pragma unroll
            for (int i = 0; i < 4; i++)
#pragma unroll
                for (int j = 0; j < 4; j++) mma8(acc[i][j], af[i], bf[j]);
        }
        __syncthreads();
    }
#pragma unroll
    for (int i = 0; i < 4; i++)
#pragma unroll
        for (int j = 0; j < 4; j++) {
            int c = bn + wn + j * 8 + lr * 2;
#pragma unroll
            for (int rr = 0; rr < 2; rr++) {
                int row = bm + wm + i * 16 + lq + rr * 8;
                atomicAdd(C + (size_t)row * ldc + c, acc[i][j][rr * 2 + 0]);
                atomicAdd(C + (size_t)row * ldc + c + 1, acc[i][j][rr * 2 + 1]);
            }
        }
}

// ================= elementwise kernels =========================================
__global__ void transpose_k(const float* __restrict__ in, float* __restrict__ out,
                            int R, int Cc) {
    __shared__ float tile[32][33];
    size_t base = (size_t)blockIdx.z * R * Cc;
    in += base; out += base;
    int c0 = blockIdx.x * 32, r0 = blockIdx.y * 32;
    int tx = threadIdx.x, ty = threadIdx.y;
#pragma unroll
    for (int j = 0; j < 32; j += 8)
        tile[ty + j][tx] = in[(size_t)(r0 + ty + j) * Cc + c0 + tx];
    __syncthreads();
#pragma unroll
    for (int j = 0; j < 32; j += 8)
        out[(size_t)(c0 + ty + j) * R + r0 + tx] = tile[tx][ty + j];
}

__global__ void softmax_k(const float* __restrict__ x, float* __restrict__ y) {
    int row = blockIdx.x * 8 + (threadIdx.x >> 5);
    int lane = threadIdx.x & 31;
    const float* xr = x + (size_t)row * Cdim;
    float v[8];
    float mx = -1e30f;
#pragma unroll
    for (int i = 0; i < 8; i++) { v[i] = xr[lane + 32 * i]; mx = fmaxf(mx, v[i]); }
#pragma unroll
    for (int o = 16; o; o >>= 1) mx = fmaxf(mx, __shfl_xor_sync(0xffffffffu, mx, o));
    float s = 0.f;
#pragma unroll
    for (int i = 0; i < 8; i++) { v[i] = __expf(v[i] - mx); s += v[i]; }
#pragma unroll
    for (int o = 16; o; o >>= 1) s += __shfl_xor_sync(0xffffffffu, s, o);
    float inv = 1.f / s;
    float* yr = y + (size_t)row * Cdim;
#pragma unroll
    for (int i = 0; i < 8; i++) yr[lane + 32 * i] = v[i] * inv;
}

// x1 -> v AND cat2[:,256:512)
__global__ void dualcopy_k() {
    int i = blockIdx.x * 256 + threadIdx.x;        // ROWS*64 float4s
    int m = i >> 6, c = i & 63;
    float4 t = ((const float4*)g_x1)[(size_t)m * 64 + c];
    ((float4*)g_v)[(size_t)m * 64 + c] = t;
    ((float4*)g_cat2)[(size_t)m * 256 + 64 + c] = t;
}

__global__ void zero_k(float* __restrict__ p, size_t n4) {
    size_t i = (size_t)blockIdx.x * blockDim.x + threadIdx.x;
    if (i < n4) ((float4*)p)[i] = make_float4(0.f, 0.f, 0.f, 0.f);
}

__global__ void prep_k(const float* __restrict__ Wres, const float* __restrict__ g1,
                       const float* __restrict__ beta1) {
    int c = blockIdx.x * 8 + (threadIdx.x >> 5);
    int lane = threadIdx.x & 31;
    const float* wr = Wres + (size_t)c * C4;
    float s1 = 0.f, s2 = 0.f;
    for (int k = lane; k < C4; k += 32) {
        float w = wr[k], g = g1[k];
        g_Wg[(size_t)c * C4 + k] = g * w;
        s1 += g * w;
        s2 += beta1[k] * w;
    }
#pragma unroll
    for (int o = 16; o; o >>= 1) {
        s1 += __shfl_xor_sync(0xffffffffu, s1, o);
        s2 += __shfl_xor_sync(0xffffffffu, s2, o);
    }
    if (lane == 0) { g_S1[c] = s1; g_S2[c] = s2; }
}

__global__ void ln1stats_k() {
    int row = blockIdx.x * 8 + (threadIdx.x >> 5);
    int lane = threadIdx.x & 31;
    const float4* r = (const float4*)(g_cat2 + (size_t)row * C4);
    float s = 0.f, sq = 0.f;
#pragma unroll
    for (int i = 0; i < 8; i++) {
        float4 t = r[lane + 32 * i];
        s += t.x + t.y + t.z + t.w;
        sq += t.x * t.x + t.y * t.y + t.z * t.z + t.w * t.w;
    }
#pragma unroll
    for (int o = 16; o; o >>= 1) {
        s += __shfl_xor_sync(0xffffffffu, s, o);
        sq += __shfl_xor_sync(0xffffffffu, sq, o);
    }
    if (lane == 0) {
        float mu = s * (1.f / 1024.f);
        float var = sq * (1.f / 1024.f) - mu * mu;
        g_mu[row] = mu;
        g_rinv[row] = rsqrtf(var + 1e-5f);
    }
}

// LN2: v = LN(u), also writes cat2[:,256:512)
__global__ void ln2_k(const float* __restrict__ g2, const float* __restrict__ b2) {
    int row = blockIdx.x * 8 + (threadIdx.x >> 5);
    int lane = threadIdx.x & 31;
    const float* ur = g_u + (size_t)row * Cdim;
    float v[8];
    float s = 0.f, sq = 0.f;
#pragma unroll
    for (int i = 0; i < 8; i++) {
        v[i] = ur[lane + 32 * i];
        s += v[i];
        sq += v[i] * v[i];
    }
#pragma unroll
    for (int o = 16; o; o >>= 1) {
        s += __shfl_xor_sync(0xffffffffu, s, o);
        sq += __shfl_xor_sync(0xffffffffu, sq, o);
    }
    float mu = s * (1.f / 256.f);
    float var = sq * (1.f / 256.f) - mu * mu;
    float rinv = rsqrtf(var + 1e-5f);
    float* vr = g_v + (size_t)row * Cdim;
    float* cr = g_cat2 + (size_t)row * C4 + 256;
#pragma unroll
    for (int i = 0; i < 8; i++) {
        int c = lane + 32 * i;
        float val = (v[i] - mu) * rinv * g2[c] + b2[c];
        vr[c] = val;
        cr[c] = val;
    }
}

// ================= host launcher ================================================
extern "C" void kernel_launch(void* const* d_in, const int* in_sizes, int n_in,
                              void* d_out, int out_size) {
    (void)in_sizes; (void)n_in; (void)out_size;
    const float* x     = (const float*)d_in[0];
    const float* Wqkv  = (const float*)d_in[1];
    const float* Wmlp  = (const float*)d_in[2];
    const float* bmlp  = (const float*)d_in[3];
    const float* g1    = (const float*)d_in[4];
    const float* beta1 = (const float*)d_in[5];
    const float* Wres  = (const float*)d_in[6];
    const float* g2    = (const float*)d_in[7];
    const float* beta2 = (const float*)d_in[8];
    float* outp = (float*)d_out;

    float *x1, *v, *sm, *u, *cat2, *ctx, *mu, *rinv, *Wg, *S1, *S2;
    cudaGetSymbolAddress((void**)&x1, g_x1);
    cudaGetSymbolAddress((void**)&v, g_v);
    cudaGetSymbolAddress((void**)&sm, g_sm);
    cudaGetSymbolAddress((void**)&u, g_u);
    cudaGetSymbolAddress((void**)&cat2, g_cat2);
    cudaGetSymbolAddress((void**)&ctx, g_ctx);
    cudaGetSymbolAddress((void**)&mu, g_mu);
    cudaGetSymbolAddress((void**)&rinv, g_rinv);
    cudaGetSymbolAddress((void**)&Wg, g_Wg);
    cudaGetSymbolAddress((void**)&S1, g_S1);
    cudaGetSymbolAddress((void**)&S2, g_S2);

    const int smemTN = 4 * 32 * 136 * 4;   // 69632 B
    cudaFuncSetAttribute(gemm_t5<0>, cudaFuncAttributeMaxDynamicSharedMemorySize, T5_SMEM);
    cudaFuncSetAttribute(gemm_t5<1>, cudaFuncAttributeMaxDynamicSharedMemorySize, T5_SMEM);
    cudaFuncSetAttribute(gemm_t5<2>, cudaFuncAttributeMaxDynamicSharedMemorySize, T5_SMEM);
    cudaFuncSetAttribute(gemm_tn<8>, cudaFuncAttributeMaxDynamicSharedMemorySize, smemTN);

    dim3 ttb(32, 8);
    transpose_k<<<dim3(Ntok / 32, Cdim / 32, Bsz), ttb>>>(x, u, Cdim, Ntok);

    // x1 = xt0 @ Wqkv^T   (M=ROWS, N=256, K=256)
    gemm_t5<0><<<dim3(2, ROWS / 128, 1), 256, T5_SMEM>>>(
        u, Cdim, 0, Wqkv, Cdim, 0, x1, Cdim, 0, Cdim,
        nullptr, nullptr, 0, nullptr, nullptr, nullptr, nullptr);

    dualcopy_k<<<ROWS * 64 / 256, 256>>>();
    softmax_k<<<ROWS / 8, 256>>>(x1, sm);
    prep_k<<<Cdim / 8, 256>>>(Wres, g1, beta1);

    for (int it = 0; it < 2; ++it) {
        // ctxT[d][c] = sum_n v[n][d] x1[n][c]  (TN split-K 8, atomic)
        zero_k<<<(Bsz * Cdim * Cdim / 4 + 255) / 256, 256>>>(ctx, (size_t)Bsz * Cdim * Cdim / 4);
        gemm_tn<8><<<dim3(2, 2, Bsz * 8), 256, smemTN>>>(
            v, Cdim, (long long)Ntok * Cdim, x1, Cdim, (long long)Ntok * Cdim,
            ctx, Cdim, (long long)Cdim * Cdim, Ntok);

        // out = sm @ ctx -> cat2[:,0:256]  (NT with B=ctxT)
        gemm_t5<0><<<dim3(2, Ntok / 128, Bsz), 256, T5_SMEM>>>(
            sm, Cdim, (long long)Ntok * Cdim, ctx, Cdim, (long long)Cdim * Cdim,
            cat2, C4, (long long)Ntok * C4, Cdim,
            nullptr, nullptr, 0, nullptr, nullptr, nullptr, nullptr);

        // mlp = relu(cat1 @ Wmlp^T + b) -> cat2[:,512:1024]  (K=512)
        gemm_t5<1><<<dim3(4, ROWS / 128, 1), 256, T5_SMEM>>>(
            cat2, C4, 0, Wmlp, 512, 0, cat2 + 512, C4, 0, 512,
            bmlp, nullptr, 0, nullptr, nullptr, nullptr, nullptr);

        ln1stats_k<<<ROWS / 8, 256>>>();

        // u = rinv*(cat2@Wg^T - mu*S1) + S2 + 2*x1  (K=1024)
        gemm_t5<2><<<dim3(2, ROWS / 128, 1), 256, T5_SMEM>>>(
            cat2, C4, 0, Wg, C4, 0, u, Cdim, 0, C4,
            nullptr, x1, Cdim, mu, rinv, S1, S2);

        ln2_k<<<ROWS / 8, 256>>>(g2, beta2);
    }

    transpose_k<<<dim3(Cdim / 32, Ntok / 32, Bsz), ttb>>>(v, outp, Ntok, Cdim);
}

// round 5
// speedup vs baseline: 10.2604x; 1.1744x over previous
#include <cuda_runtime.h>
#include <math.h>
#include <stdint.h>

#define Bsz  8
#define Cdim 256
#define Ntok 4096
#define ROWS (Bsz * Ntok)          // 32768 token rows
#define C4   (4 * Cdim)            // 1024

// ---------------- scratch (static device arrays; no allocation) ----------------
__device__ float g_x1[(size_t)ROWS * Cdim];
__device__ float g_sm[(size_t)ROWS * Cdim];
__device__ float g_u[(size_t)ROWS * Cdim];
__device__ float g_cat2[(size_t)ROWS * C4];        // [out | v | mlp], ld=1024
__device__ float g_ctx[(size_t)Bsz * Cdim * Cdim]; // ctxT[d][c]
__device__ float g_mu[ROWS];
__device__ float g_rinv[ROWS];
__device__ float g_Wg[(size_t)Cdim * C4];
__device__ float g_S1[Cdim];
__device__ float g_S2[Cdim];
// LN1 stat accumulators: [rsum0 | rsq0 | rsum1 | rsq1]
__device__ float g_stats[4 * ROWS];

#if defined(__CUDA_ARCH_FEAT_SM103_ALL) || defined(__CUDA_ARCH_FEAT_SM100_ALL)
#define HAS_TCGEN05 1
#else
#define HAS_TCGEN05 0
#endif

// ================= helpers ======================================================
__device__ __forceinline__ uint32_t smem_u32(const void* p) {
    return (uint32_t)__cvta_generic_to_shared(p);
}
__device__ __forceinline__ uint32_t elect1() {
    uint32_t pred;
    asm volatile("{\n\t.reg .pred p;\n\telect.sync _|p, 0xFFFFFFFF;\n\tselp.b32 %0, 1, 0, p;\n\t}"
                 : "=r"(pred));
    return pred;
}
__device__ __forceinline__ void mbar_init(uint32_t a, uint32_t cnt) {
    asm volatile("mbarrier.init.shared.b64 [%0], %1;" :: "r"(a), "r"(cnt) : "memory");
}
__device__ __forceinline__ void mbar_wait(uint32_t a, int ph) {
    asm volatile(
        "{\n\t.reg .pred P;\n\t"
        "WL%=:\n\t"
        "mbarrier.try_wait.parity.acquire.cta.shared::cta.b64 P, [%0], %1, 0x989680;\n\t"
        "@P bra.uni WD%=;\n\t"
        "bra.uni WL%=;\n\t"
        "WD%=:\n\t}"
        :: "r"(a), "r"(ph) : "memory");
}
#define SW128B(o) ((o) ^ (((o) >> 3) & 0x70))

static constexpr unsigned long long DESC_SW128 =
    (2ull << 61) | (1ull << 46) | (64ull << 32) | (1ull << 16);
__device__ __forceinline__ uint64_t mk_desc(uint32_t addr) {
    return DESC_SW128 | ((uint64_t)(addr >> 4) & 0x3FFF);
}

__device__ __forceinline__ uint32_t cvt_tf32(float x) {
    uint32_t r;
    asm("cvt.rna.tf32.f32 %0, %1;" : "=r"(r) : "f"(x));
    return r;
}
__device__ __forceinline__ void cp16(float* s, const float* g) {
    uint32_t sa = smem_u32(s);
    asm volatile("cp.async.cg.shared.global [%0], [%1], 16;" :: "r"(sa), "l"(g));
}
__device__ __forceinline__ void cp16s(uint32_t sa, const float* g) {
    asm volatile("cp.async.cg.shared.global [%0], [%1], 16;" :: "r"(sa), "l"(g));
}
__device__ __forceinline__ void cp_commit() { asm volatile("cp.async.commit_group;" ::); }
template <int N>
__device__ __forceinline__ void cp_wait() { asm volatile("cp.async.wait_group %0;" :: "n"(N)); }

__device__ __forceinline__ void mma8(float* c, const uint32_t* a, const uint32_t* b) {
    asm volatile(
        "mma.sync.aligned.m16n8k8.row.col.f32.tf32.tf32.f32 "
        "{%0,%1,%2,%3}, {%4,%5,%6,%7}, {%8,%9}, {%0,%1,%2,%3};"
        : "+f"(c[0]), "+f"(c[1]), "+f"(c[2]), "+f"(c[3])
        : "r"(a[0]), "r"(a[1]), "r"(a[2]), "r"(a[3]), "r"(b[0]), "r"(b[1]));
}

// ================= unified NT GEMM, CTA tile 128x256 ===========================
// C[m][n] = sum_k A[m*lda+k] * B[n*ldb+k]
// EPI bits: 1=relu+bias, 2=LN-residual epi, 4=accumulate LN1 row stats
// smem: 1024 ctrl + 2 stages x (A 16K + B 32K) = 99328 B
#define T5_SMEM 99328

#if HAS_TCGEN05
__device__ __forceinline__ void tc_stage(const float* __restrict__ A, int lda,
                                         const float* __restrict__ B, int ldb,
                                         int bm, int bn, int k0,
                                         char* smem, int sbase, int tid) {
#pragma unroll
    for (int i = 0; i < 4; i++) {
        int c = tid + i * 256;
        int row = c >> 3, in16 = c & 7;
        uint32_t so = SW128B((uint32_t)(row * 128 + in16 * 16));
        cp16s(smem_u32(smem + sbase + so), A + (size_t)(bm + row) * lda + k0 + in16 * 4);
    }
#pragma unroll
    for (int i = 0; i < 8; i++) {
        int c = tid + i * 256;
        int row = c >> 3, in16 = c & 7;
        uint32_t so = SW128B((uint32_t)(row * 128 + in16 * 16));
        cp16s(smem_u32(smem + sbase + 16384 + so), B + (size_t)(bn + row) * ldb + k0 + in16 * 4);
    }
    cp_commit();
}
#endif

// legacy fallback staging (128-wide n-half)
__device__ __forceinline__ void nt_stage(const float* __restrict__ A, int lda,
                                         const float* __restrict__ B, int ldb,
                                         int bm, int bn, int k0,
                                         float* as, float* bs, int tid) {
#pragma unroll
    for (int i = 0; i < 4; i++) {
        int idx = tid + i * 256;
        int row = idx >> 3, c4 = (idx & 7) << 2;
        cp16(as + row * 36 + c4, A + (size_t)(bm + row) * lda + k0 + c4);
        cp16(bs + row * 36 + c4, B + (size_t)(bn + row) * ldb + k0 + c4);
    }
    cp_commit();
}

template <int EPI>
__global__ __launch_bounds__(256)
void gemm_t5(const float* __restrict__ A, int lda, long long sA,
             const float* __restrict__ B, int ldb, long long sB,
             float* __restrict__ C, int ldc, long long sC, int K,
             const float* __restrict__ bias,
             const float* __restrict__ resid, int ldr,
             const float* __restrict__ mu, const float* __restrict__ rinv,
             const float* __restrict__ S1, const float* __restrict__ S2,
             float* __restrict__ rsum, float* __restrict__ rsq, long long sStat) {
    extern __shared__ char smem[];
    const int tid = threadIdx.x, wid = tid >> 5, lane = tid & 31;
    const int bz = blockIdx.z;
    A += (size_t)bz * sA;
    B += (size_t)bz * sB;
    C += (size_t)bz * sC;
    if (EPI & 4) { rsum += (size_t)bz * sStat; rsq += (size_t)bz * sStat; }
    const int bm = blockIdx.y * 128, bn = blockIdx.x * 256;

#if HAS_TCGEN05
    uint32_t sb = smem_u32(smem);
    if (wid == 0) {
        asm volatile("tcgen05.alloc.cta_group::1.sync.aligned.shared::cta.b32 [%0], %1;"
                     :: "r"(sb), "r"(256) : "memory");
        asm volatile("tcgen05.relinquish_alloc_permit.cta_group::1.sync.aligned;");
    }
    if (tid == 0) { mbar_init(sb + 8, 1); mbar_init(sb + 16, 1); }
    __syncthreads();
    uint32_t tmem;
    asm volatile("ld.shared.b32 %0, [%1];" : "=r"(tmem) : "r"(sb));

    const int KT = K / 32;
    tc_stage(A, lda, B, ldb, bm, bn, 0, smem, 1024, tid);
    tc_stage(A, lda, B, ldb, bm, bn, 32, smem, 1024 + 49152, tid);
    int ph0 = 0, ph1 = 0;
    // idesc: dtype=F32(1)<<4, a/btype=TF32(2), N/8<<17 (N=256 -> 32), M/16<<24
    const uint32_t IDESC = (1u << 4) | (2u << 7) | (2u << 10) | (32u << 17) | (8u << 24);

    for (int kt = 0; kt < KT; kt++) {
        int buf = kt & 1;
        if (kt == KT - 1) cp_wait<0>(); else cp_wait<1>();
        asm volatile("fence.proxy.async.shared::cta;" ::: "memory");
        __syncthreads();
        if (wid == 0 && elect1()) {
            uint64_t ad = mk_desc(sb + 1024 + buf * 49152);
            uint64_t bd = mk_desc(sb + 1024 + buf * 49152 + 16384);
#pragma unroll
            for (int s = 0; s < 4; s++) {
                uint32_t en = (kt > 0 || s > 0) ? 1u : 0u;
                asm volatile(
                    "{\n\t.reg .pred p;\n\tsetp.ne.u32 p, %5, 0;\n\t"
                    "tcgen05.mma.cta_group::1.kind::tf32 [%0], %1, %2, %3, {%4,%4,%4,%4}, p;\n\t}"
                    :: "r"(tmem), "l"(ad + s * 2), "l"(bd + s * 2), "r"(IDESC),
                       "r"(0u), "r"(en) : "memory");
            }
            asm volatile(
                "tcgen05.commit.cta_group::1.mbarrier::arrive::one.shared::cluster.b64 [%0];"
                :: "r"(sb + 8 + buf * 8) : "memory");
        }
        if (kt + 2 < KT) {
            if (buf == 0) { mbar_wait(sb + 8, ph0); ph0 ^= 1; }
            else          { mbar_wait(sb + 16, ph1); ph1 ^= 1; }
            tc_stage(A, lda, B, ldb, bm, bn, (kt + 2) * 32, smem, 1024 + buf * 49152, tid);
        }
    }
    int lb = (KT - 1) & 1;
    if (lb == 0) mbar_wait(sb + 8, ph0); else mbar_wait(sb + 16, ph1);
    asm volatile("tcgen05.fence::after_thread_sync;" ::: "memory");

    // epilogue: warp w -> TMEM subpartition (w&3): rows bm+(w&3)*32+lane,
    // column block (w>>2)*128; 4 chunks of 32 cols each.
    const int row = bm + (wid & 3) * 32 + lane;
    const int cb = (wid >> 2) * 128;
    float rv = 0.f, mm = 0.f;
    if (EPI & 2) { rv = rinv[row]; mm = mu[row]; }
    float ssum = 0.f, ssq = 0.f;
#pragma unroll
    for (int cc = 0; cc < 4; cc++) {
        int c0 = cb + cc * 32;
        uint32_t d[32];
        asm volatile(
            "tcgen05.ld.sync.aligned.32x32b.x32.b32 "
            "{%0, %1, %2, %3, %4, %5, %6, %7, "
            " %8, %9, %10, %11, %12, %13, %14, %15, "
            " %16, %17, %18, %19, %20, %21, %22, %23, "
            " %24, %25, %26, %27, %28, %29, %30, %31}, [%32];"
            : "=r"(d[0]), "=r"(d[1]), "=r"(d[2]), "=r"(d[3]),
              "=r"(d[4]), "=r"(d[5]), "=r"(d[6]), "=r"(d[7]),
              "=r"(d[8]), "=r"(d[9]), "=r"(d[10]), "=r"(d[11]),
              "=r"(d[12]), "=r"(d[13]), "=r"(d[14]), "=r"(d[15]),
              "=r"(d[16]), "=r"(d[17]), "=r"(d[18]), "=r"(d[19]),
              "=r"(d[20]), "=r"(d[21]), "=r"(d[22]), "=r"(d[23]),
              "=r"(d[24]), "=r"(d[25]), "=r"(d[26]), "=r"(d[27]),
              "=r"(d[28]), "=r"(d[29]), "=r"(d[30]), "=r"(d[31])
            : "r"(tmem + c0));
        asm volatile("tcgen05.wait::ld.sync.aligned;" ::: "memory");
#pragma unroll
        for (int j = 0; j < 32; j += 4) {
            int c = bn + c0 + j;
            float4 o;
            float* ov = &o.x;
#pragma unroll
            for (int q = 0; q < 4; q++) {
                float val = __uint_as_float(d[j + q]);
                if (EPI & 1) val = fmaxf(val + bias[c + q], 0.f);
                if (EPI & 2) val = fmaf(rv, val - mm * S1[c + q], S2[c + q]);
                ov[q] = val;
            }
            if (EPI & 2) {
                const float4 rp = *(const float4*)(resid + (size_t)row * ldr + c);
                o.x += 2.f * rp.x; o.y += 2.f * rp.y;
                o.z += 2.f * rp.z; o.w += 2.f * rp.w;
            }
            if (EPI & 4) {
                ssum += o.x + o.y + o.z + o.w;
                ssq += o.x * o.x + o.y * o.y + o.z * o.z + o.w * o.w;
            }
            *(float4*)(C + (size_t)row * ldc + c) = o;
        }
    }
    if (EPI & 4) {
        atomicAdd(rsum + row, ssum);
        atomicAdd(rsq + row, ssq);
    }
    __syncthreads();
    if (wid == 0) {
        asm volatile("tcgen05.dealloc.cta_group::1.sync.aligned.b32 %0, %1;"
                     :: "r"(tmem), "r"(256));
    }
#else
    // ---------- legacy fallback: two 128-wide n-halves ----------
    float* fsm = (float*)smem;
    constexpr int ABUF = 128 * 36;
    float* As = fsm;
    float* Bs = fsm + 2 * ABUF;
    const int wm = (wid >> 2) * 64, wn = (wid & 3) * 32;
    const int lq = lane >> 2, lr = lane & 3;
    for (int half = 0; half < 2; half++) {
        int bnh = bn + half * 128;
        float acc[4][4][4];
#pragma unroll
        for (int i = 0; i < 4; i++)
#pragma unroll
            for (int j = 0; j < 4; j++)
#pragma unroll
                for (int t = 0; t < 4; t++) acc[i][j][t] = 0.f;
        const int KT = K / 32;
        nt_stage(A, lda, B, ldb, bm, bnh, 0, As, Bs, tid);
        for (int kt = 0; kt < KT; kt++) {
            int buf = kt & 1;
            if (kt + 1 < KT) {
                nt_stage(A, lda, B, ldb, bm, bnh, (kt + 1) * 32,
                         As + ((kt + 1) & 1) * ABUF, Bs + ((kt + 1) & 1) * ABUF, tid);
                cp_wait<1>();
            } else cp_wait<0>();
            __syncthreads();
            const float* as = As + buf * ABUF;
            const float* bs = Bs + buf * ABUF;
#pragma unroll
            for (int kk = 0; kk < 4; kk++) {
                const int k0 = kk * 8;
                uint32_t af[4][4], bf[4][2];
#pragma unroll
                for (int i = 0; i < 4; i++) {
                    const float* p = as + (wm + i * 16 + lq) * 36 + k0 + lr;
                    af[i][0] = cvt_tf32(p[0]);
                    af[i][2] = cvt_tf32(p[4]);
                    const float* p8 = p + 8 * 36;
                    af[i][1] = cvt_tf32(p8[0]);
                    af[i][3] = cvt_tf32(p8[4]);
                }
#pragma unroll
                for (int j = 0; j < 4; j++) {
                    const float* p = bs + (wn + j * 8 + lq) * 36 + k0 + lr;
                    bf[j][0] = cvt_tf32(p[0]);
                    bf[j][1] = cvt_tf32(p[4]);
                }
#pragma unroll
                for (int i = 0; i < 4; i++)
#pragma unroll
                    for (int j = 0; j < 4; j++) mma8(acc[i][j], af[i], bf[j]);
            }
            __syncthreads();
        }
#pragma unroll
        for (int i = 0; i < 4; i++) {
#pragma unroll
            for (int j = 0; j < 4; j++) {
                int c = bnh + wn + j * 8 + lr * 2;
#pragma unroll
                for (int rr = 0; rr < 2; rr++) {
                    int row = bm + wm + i * 16 + lq + rr * 8;
                    float v0 = acc[i][j][rr * 2 + 0], v1 = acc[i][j][rr * 2 + 1];
                    if (EPI & 1) {
                        v0 = fmaxf(v0 + bias[c], 0.f);
                        v1 = fmaxf(v1 + bias[c + 1], 0.f);
                    }
                    if (EPI & 2) {
                        float rv = rinv[row], m_ = mu[row];
                        const float* rp = resid + (size_t)row * ldr + c;
                        v0 = fmaf(rv, v0 - m_ * S1[c], S2[c]) + 2.f * rp[0];
                        v1 = fmaf(rv, v1 - m_ * S1[c + 1], S2[c + 1]) + 2.f * rp[1];
                    }
                    if (EPI & 4) {
                        atomicAdd(rsum + row, v0 + v1);
                        atomicAdd(rsq + row, v0 * v0 + v1 * v1);
                    }
                    *(float2*)(C + (size_t)row * ldc + c) = make_float2(v0, v1);
                }
            }
        }
        __syncthreads();
    }
#endif
}

// ================= legacy tf32 warp-MMA GEMM (TN, split-K, atomic) =============
__device__ __forceinline__ void stage_tn(const float* __restrict__ A, int lda,
                                         const float* __restrict__ B, int ldb,
                                         int bm, int bn, int k0,
                                         float* as, float* bs, int tid) {
#pragma unroll
    for (int i = 0; i < 4; i++) {
        int idx = tid + i * 256;
        int row = idx >> 5, c4 = (idx & 31) << 2;
        cp16(as + row * 136 + c4, A + (size_t)(k0 + row) * lda + bm + c4);
        cp16(bs + row * 136 + c4, B + (size_t)(k0 + row) * ldb + bn + c4);
    }
    cp_commit();
}
template <int SPLITK>
__global__ __launch_bounds__(256, 2)
void gemm_tn(const float* __restrict__ A, int lda, long long sA,
             const float* __restrict__ B, int ldb, long long sB,
             float* __restrict__ C, int ldc, long long sC, int K) {
    extern __shared__ float fsm[];
    constexpr int ABUF = 32 * 136;
    float* As = fsm;
    float* Bs = fsm + 2 * ABUF;
    int bz = blockIdx.z;
    int batch = bz / SPLITK, ks = bz - batch * SPLITK;
    A += (size_t)batch * sA;
    B += (size_t)batch * sB;
    C += (size_t)batch * sC;
    const int kchunk = K / SPLITK, kbase = ks * kchunk;
    const int bm = blockIdx.y * 128, bn = blockIdx.x * 128;
    const int tid = threadIdx.x, wid = tid >> 5, lane = tid & 31;
    const int wm = (wid >> 2) * 64, wn = (wid & 3) * 32;
    const int lq = lane >> 2, lr = lane & 3;
    float acc[4][4][4];
#pragma unroll
    for (int i = 0; i < 4; i++)
#pragma unroll
        for (int j = 0; j < 4; j++)
#pragma unroll
            for (int t = 0; t < 4; t++) acc[i][j][t] = 0.f;
    const int KT = kchunk / 32;
    stage_tn(A, lda, B, ldb, bm, bn, kbase, As, Bs, tid);
    for (int kt = 0; kt < KT; kt++) {
        int buf = kt & 1;
        if (kt + 1 < KT) {
            stage_tn(A, lda, B, ldb, bm, bn, kbase + (kt + 1) * 32,
                     As + ((kt + 1) & 1) * ABUF, Bs + ((kt + 1) & 1) * ABUF, tid);
            cp_wait<1>();
        } else cp_wait<0>();
        __syncthreads();
        const float* as = As + buf * ABUF;
        const float* bs = Bs + buf * ABUF;
#pragma unroll
        for (int kk = 0; kk < 4; kk++) {
            const int k0 = kk * 8;
            uint32_t af[4][4], bf[4][2];
#pragma unroll
            for (int i = 0; i < 4; i++) {
                const float* p = as + (k0 + lr) * 136 + wm + i * 16 + lq;
                af[i][0] = cvt_tf32(p[0]);
                af[i][1] = cvt_tf32(p[8]);
                const float* p4 = p + 4 * 136;
                af[i][2] = cvt_tf32(p4[0]);
                af[i][3] = cvt_tf32(p4[8]);
            }
#pragma unroll
            for (int j = 0; j < 4; j++) {
                const float* p = bs + (k0 + lr) * 136 + wn + j * 8 + lq;
                bf[j][0] = cvt_tf32(p[0]);
                bf[j][1] = cvt_tf32(p[4 * 136]);
            }
#pragma unroll
            for (int i = 0; i < 4; i++)
#pragma unroll
                for (int j = 0; j < 4; j++) mma8(acc[i][j], af[i], bf[j]);
        }
        __syncthreads();
    }
#pragma unroll
    for (int i = 0; i < 4; i++)
#pragma unroll
        for (int j = 0; j < 4; j++) {
            int c = bn + wn + j * 8 + lr * 2;
#pragma unroll
            for (int rr = 0; rr < 2; rr++) {
                int row = bm + wm + i * 16 + lq + rr * 8;
                atomicAdd(C + (size_t)row * ldc + c, acc[i][j][rr * 2 + 0]);
                atomicAdd(C + (size_t)row * ldc + c + 1, acc[i][j][rr * 2 + 1]);
            }
        }
}

// ================= elementwise kernels =========================================
// in: R x Cc rows with row-stride ldin, batch stride sIn; out: Cc x R contiguous.
__global__ void transpose_k(const float* __restrict__ in, float* __restrict__ out,
                            int R, int Cc, int ldin, long long sIn, long long sOut) {
    __shared__ float tile[32][33];
    in += (size_t)blockIdx.z * sIn;
    out += (size_t)blockIdx.z * sOut;
    int c0 = blockIdx.x * 32, r0 = blockIdx.y * 32;
    int tx = threadIdx.x, ty = threadIdx.y;
#pragma unroll
    for (int j = 0; j < 32; j += 8)
        tile[ty + j][tx] = in[(size_t)(r0 + ty + j) * ldin + c0 + tx];
    __syncthreads();
#pragma unroll
    for (int j = 0; j < 32; j += 8)
        out[(size_t)(c0 + ty + j) * R + r0 + tx] = tile[tx][ty + j];
}

__global__ void softmax_k(const float* __restrict__ x, float* __restrict__ y) {
    int row = blockIdx.x * 8 + (threadIdx.x >> 5);
    int lane = threadIdx.x & 31;
    const float* xr = x + (size_t)row * Cdim;
    float v[8];
    float mx = -1e30f;
#pragma unroll
    for (int i = 0; i < 8; i++) { v[i] = xr[lane + 32 * i]; mx = fmaxf(mx, v[i]); }
#pragma unroll
    for (int o = 16; o; o >>= 1) mx = fmaxf(mx, __shfl_xor_sync(0xffffffffu, mx, o));
    float s = 0.f;
#pragma unroll
    for (int i = 0; i < 8; i++) { v[i] = __expf(v[i] - mx); s += v[i]; }
#pragma unroll
    for (int o = 16; o; o >>= 1) s += __shfl_xor_sync(0xffffffffu, s, o);
    float inv = 1.f / s;
    float* yr = y + (size_t)row * Cdim;
#pragma unroll
    for (int i = 0; i < 8; i++) yr[lane + 32 * i] = v[i] * inv;
}

// x1 -> cat2[:,256:512) + LN1 stats (buf0). Each warp covers half a row.
__global__ void vcopy_k(float* __restrict__ rsum, float* __restrict__ rsq) {
    int i = blockIdx.x * 256 + threadIdx.x;     // ROWS*64 float4s
    int m = i >> 6, c = i & 63;
    float4 t = ((const float4*)g_x1)[(size_t)m * 64 + c];
    ((float4*)g_cat2)[(size_t)m * 256 + 64 + c] = t;
    float s = t.x + t.y + t.z + t.w;
    float q = t.x * t.x + t.y * t.y + t.z * t.z + t.w * t.w;
#pragma unroll
    for (int o = 16; o; o >>= 1) {
        s += __shfl_xor_sync(0xffffffffu, s, o);
        q += __shfl_xor_sync(0xffffffffu, q, o);
    }
    if ((threadIdx.x & 31) == 0) {
        atomicAdd(rsum + m, s);
        atomicAdd(rsq + m, q);
    }
}

__global__ void zero_k(float* __restrict__ p, size_t n4) {
    size_t i = (size_t)blockIdx.x * blockDim.x + threadIdx.x;
    if (i < n4) ((float4*)p)[i] = make_float4(0.f, 0.f, 0.f, 0.f);
}

__global__ void prep_k(const float* __restrict__ Wres, const float* __restrict__ g1,
                       const float* __restrict__ beta1) {
    int c = blockIdx.x * 8 + (threadIdx.x >> 5);
    int lane = threadIdx.x & 31;
    const float* wr = Wres + (size_t)c * C4;
    float s1 = 0.f, s2 = 0.f;
    for (int k = lane; k < C4; k += 32) {
        float w = wr[k], g = g1[k];
        g_Wg[(size_t)c * C4 + k] = g * w;
        s1 += g * w;
        s2 += beta1[k] * w;
    }
#pragma unroll
    for (int o = 16; o; o >>= 1) {
        s1 += __shfl_xor_sync(0xffffffffu, s1, o);
        s2 += __shfl_xor_sync(0xffffffffu, s2, o);
    }
    if (lane == 0) { g_S1[c] = s1; g_S2[c] = s2; }
}

// mu/rinv from accumulated stats
__global__ void finalize_k(const float* __restrict__ rsum, const float* __restrict__ rsq) {
    int row = blockIdx.x * 256 + threadIdx.x;
    float mu = rsum[row] * (1.f / 1024.f);
    float var = rsq[row] * (1.f / 1024.f) - mu * mu;
    g_mu[row] = mu;
    g_rinv[row] = rsqrtf(var + 1e-5f);
}

// LN2: cat2[:,256:512) = LN(u); optionally accumulate stats for next iter
__global__ void ln2_k(const float* __restrict__ g2, const float* __restrict__ b2,
                      float* __restrict__ rsum, float* __restrict__ rsq) {
    int row = blockIdx.x * 8 + (threadIdx.x >> 5);
    int lane = threadIdx.x & 31;
    const float* ur = g_u + (size_t)row * Cdim;
    float v[8];
    float s = 0.f, sq = 0.f;
#pragma unroll
    for (int i = 0; i < 8; i++) {
        v[i] = ur[lane + 32 * i];
        s += v[i];
        sq += v[i] * v[i];
    }
#pragma unroll
    for (int o = 16; o; o >>= 1) {
        s += __shfl_xor_sync(0xffffffffu, s, o);
        sq += __shfl_xor_sync(0xffffffffu, sq, o);
    }
    float mu = s * (1.f / 256.f);
    float var = sq * (1.f / 256.f) - mu * mu;
    float rinv = rsqrtf(var + 1e-5f);
    float* cr = g_cat2 + (size_t)row * C4 + 256;
    float vs = 0.f, vq = 0.f;
#pragma unroll
    for (int i = 0; i < 8; i++) {
        int c = lane + 32 * i;
        float val = (v[i] - mu) * rinv * g2[c] + b2[c];
        cr[c] = val;
        vs += val;
        vq += val * val;
    }
    if (rsum) {
#pragma unroll
        for (int o = 16; o; o >>= 1) {
            vs += __shfl_xor_sync(0xffffffffu, vs, o);
            vq += __shfl_xor_sync(0xffffffffu, vq, o);
        }
        if (lane == 0) {
            atomicAdd(rsum + row, vs);
            atomicAdd(rsq + row, vq);
        }
    }
}

// ================= host launcher ================================================
extern "C" void kernel_launch(void* const* d_in, const int* in_sizes, int n_in,
                              void* d_out, int out_size) {
    (void)in_sizes; (void)n_in; (void)out_size;
    const float* x     = (const float*)d_in[0];
    const float* Wqkv  = (const float*)d_in[1];
    const float* Wmlp  = (const float*)d_in[2];
    const float* bmlp  = (const float*)d_in[3];
    const float* g1    = (const float*)d_in[4];
    const float* beta1 = (const float*)d_in[5];
    const float* Wres  = (const float*)d_in[6];
    const float* g2    = (const float*)d_in[7];
    const float* beta2 = (const float*)d_in[8];
    float* outp = (float*)d_out;

    float *x1, *sm, *u, *cat2, *ctx, *mu, *rinv, *Wg, *S1, *S2, *stats;
    cudaGetSymbolAddress((void**)&x1, g_x1);
    cudaGetSymbolAddress((void**)&sm, g_sm);
    cudaGetSymbolAddress((void**)&u, g_u);
    cudaGetSymbolAddress((void**)&cat2, g_cat2);
    cudaGetSymbolAddress((void**)&ctx, g_ctx);
    cudaGetSymbolAddress((void**)&mu, g_mu);
    cudaGetSymbolAddress((void**)&rinv, g_rinv);
    cudaGetSymbolAddress((void**)&Wg, g_Wg);
    cudaGetSymbolAddress((void**)&S1, g_S1);
    cudaGetSymbolAddress((void**)&S2, g_S2);
    cudaGetSymbolAddress((void**)&stats, g_stats);
    float* rsum0 = stats;
    float* rsq0  = stats + ROWS;
    float* rsum1 = stats + 2 * ROWS;
    float* rsq1  = stats + 3 * ROWS;

    const int smemTN = 4 * 32 * 136 * 4;   // 69632 B
    cudaFuncSetAttribute(gemm_t5<0>, cudaFuncAttributeMaxDynamicSharedMemorySize, T5_SMEM);
    cudaFuncSetAttribute(gemm_t5<4>, cudaFuncAttributeMaxDynamicSharedMemorySize, T5_SMEM);
    cudaFuncSetAttribute(gemm_t5<5>, cudaFuncAttributeMaxDynamicSharedMemorySize, T5_SMEM);
    cudaFuncSetAttribute(gemm_t5<2>, cudaFuncAttributeMaxDynamicSharedMemorySize, T5_SMEM);
    cudaFuncSetAttribute(gemm_tn<8>, cudaFuncAttributeMaxDynamicSharedMemorySize, smemTN);

    float* vbuf = cat2 + 256;   // v lives in cat2[:,256:512), ld C4

    dim3 ttb(32, 8);
    // xt0 (B,N,C) from x (B,C,N); scratch in g_u
    transpose_k<<<dim3(Ntok / 32, Cdim / 32, Bsz), ttb>>>(
        x, u, Cdim, Ntok, Ntok, (long long)Cdim * Ntok, (long long)Cdim * Ntok);

    // x1 = xt0 @ Wqkv^T   (M=ROWS, N=256, K=256)
    gemm_t5<0><<<dim3(1, ROWS / 128, 1), 256, T5_SMEM>>>(
        u, Cdim, 0, Wqkv, Cdim, 0, x1, Cdim, 0, Cdim,
        nullptr, nullptr, 0, nullptr, nullptr, nullptr, nullptr, nullptr, nullptr, 0);

    zero_k<<<(4 * ROWS / 4 + 255) / 256, 256>>>(stats, 4 * ROWS / 4);
    vcopy_k<<<ROWS * 64 / 256, 256>>>(rsum0, rsq0);
    softmax_k<<<ROWS / 8, 256>>>(x1, sm);
    prep_k<<<Cdim / 8, 256>>>(Wres, g1, beta1);

    for (int it = 0; it < 2; ++it) {
        float* rs = it == 0 ? rsum0 : rsum1;
        float* rq = it == 0 ? rsq0 : rsq1;

        // ctxT[d][c] = sum_n v[n][d] x1[n][c]  (TN split-K 8, atomic); v from cat2
        zero_k<<<(Bsz * Cdim * Cdim / 4 + 255) / 256, 256>>>(ctx, (size_t)Bsz * Cdim * Cdim / 4);
        gemm_tn<8><<<dim3(2, 2, Bsz * 8), 256, smemTN>>>(
            vbuf, C4, (long long)Ntok * C4, x1, Cdim, (long long)Ntok * Cdim,
            ctx, Cdim, (long long)Cdim * Cdim, Ntok);

        // out = sm @ ctx -> cat2[:,0:256], + stats
        gemm_t5<4><<<dim3(1, Ntok / 128, Bsz), 256, T5_SMEM>>>(
            sm, Cdim, (long long)Ntok * Cdim, ctx, Cdim, (long long)Cdim * Cdim,
            cat2, C4, (long long)Ntok * C4, Cdim,
            nullptr, nullptr, 0, nullptr, nullptr, nullptr, nullptr, rs, rq, Ntok);

        // mlp = relu(cat1 @ Wmlp^T + b) -> cat2[:,512:1024], + stats (K=512)
        gemm_t5<5><<<dim3(2, ROWS / 128, 1), 256, T5_SMEM>>>(
            cat2, C4, 0, Wmlp, 512, 0, cat2 + 512, C4, 0, 512,
            bmlp, nullptr, 0, nullptr, nullptr, nullptr, nullptr, rs, rq, 0);

        finalize_k<<<ROWS / 256, 256>>>(rs, rq);

        // u = rinv*(cat2@Wg^T - mu*S1) + S2 + 2*x1  (K=1024)
        gemm_t5<2><<<dim3(1, ROWS / 128, 1), 256, T5_SMEM>>>(
            cat2, C4, 0, Wg, C4, 0, u, Cdim, 0, C4,
            nullptr, x1, Cdim, mu, rinv, S1, S2, nullptr, nullptr, 0);

        // v = LN2(u) -> cat2[:,256:512), stats for next iter (only needed it=0)
        ln2_k<<<ROWS / 8, 256>>>(g2, beta2, it == 0 ? rsum1 : nullptr,
                                 it == 0 ? rsq1 : nullptr);
    }

    // output (B,C,N) from v (strided in cat2)
    transpose_k<<<dim3(Cdim / 32, Ntok / 32, Bsz), ttb>>>(
        vbuf, outp, Ntok, Cdim, C4, (long long)Ntok * C4, (long long)Ntok * Cdim);
}